// round 6
// baseline (speedup 1.0000x reference)
#include <cuda_runtime.h>
#include <cuda_fp16.h>
#include <cstdint>
#include <cstddef>

#define LSEQ 512
#define NBATCH 512
#define IDIM 128
#define HDIM 128
#define GDIM 512   // 4*H

// Scratch: packed fp16 pre-activation input gates.
// Layout: [m = t*N+n][hcol 0..127][gate 0..3]  -> 8 bytes per (m, hcol)
__device__ __half g_XgH[(size_t)LSEQ * NBATCH * GDIM];

// ---------------------------------------------------------------------------
// helpers
// ---------------------------------------------------------------------------
__device__ __forceinline__ uint32_t f2h2(float a, float b) {
    __half2 h = __floats2half2_rn(a, b);
    return *reinterpret_cast<uint32_t*>(&h);
}

__device__ __forceinline__ void mma16816(float* d,
    uint32_t a0, uint32_t a1, uint32_t a2, uint32_t a3,
    uint32_t b0, uint32_t b1)
{
    asm volatile(
        "mma.sync.aligned.m16n8k16.row.col.f32.f16.f16.f32 "
        "{%0,%1,%2,%3}, {%4,%5,%6,%7}, {%8,%9}, {%0,%1,%2,%3};\n"
        : "+f"(d[0]), "+f"(d[1]), "+f"(d[2]), "+f"(d[3])
        : "r"(a0), "r"(a1), "r"(a2), "r"(a3), "r"(b0), "r"(b1));
}

__device__ __forceinline__ void ldsm4(uint32_t& a0, uint32_t& a1,
                                      uint32_t& a2, uint32_t& a3, uint32_t saddr)
{
    asm volatile("ldmatrix.sync.aligned.m8n8.x4.shared.b16 {%0,%1,%2,%3}, [%4];"
                 : "=r"(a0), "=r"(a1), "=r"(a2), "=r"(a3) : "r"(saddr));
}

__device__ __forceinline__ float ex2f(float x) {
    float y; asm("ex2.approx.f32 %0, %1;" : "=f"(y) : "f"(x)); return y;
}
__device__ __forceinline__ float rcpf(float x) {
    float y; asm("rcp.approx.f32 %0, %1;" : "=f"(y) : "f"(x)); return y;
}
// accurate sigmoid/tanh (EX2 ~2ulp, RCP ~1ulp) — NOT tanh.approx
__device__ __forceinline__ float sigf(float x) {
    return rcpf(1.0f + ex2f(-1.44269504f * x));
}
__device__ __forceinline__ float tanh_fast(float x) {
    return __fmaf_rn(2.0f, sigf(2.0f * x), -1.0f);
}

// ---------------------------------------------------------------------------
// Phase 1: Xg = x@W_ih^T + (b_ih+b_hh), packed fp16 [m][hcol][gate].
// Grid 1024 x 512 threads. 256 M-rows/block, 8 subtiles of 32, double-buffered
// A smem with register prefetch. Warp w owns hcols [8w,8w+8) for all 4 gates.
// ---------------------------------------------------------------------------
__global__ void __launch_bounds__(512, 1)
pregemm_kernel(const float* __restrict__ x,
               const float* __restrict__ Wih,
               const float* __restrict__ bih,
               const float* __restrict__ bhh)
{
    __shared__ __half Ash[2][32][136];   // 272B pitch, conflict-free

    const int tid  = threadIdx.x;
    const int warp = tid >> 5;
    const int lane = tid & 31;
    const int q    = lane & 3;
    const int r0   = lane >> 2;
    const int c0   = warp * 8 + q * 2;   // hcol pair base (per-gate col)

    // --- B fragments: W_ih rows for gate tiles j at cols j*128 + [8w,8w+8) ---
    uint32_t bfrag[4][8][2];
#pragma unroll
    for (int j = 0; j < 4; j++) {
        const float* wr = Wih + (size_t)(j * 128 + warp * 8 + r0) * IDIM;
#pragma unroll
        for (int kt = 0; kt < 8; kt++) {
            const int k = kt * 16 + q * 2;
            float2 w0 = *reinterpret_cast<const float2*>(wr + k);
            float2 w1 = *reinterpret_cast<const float2*>(wr + k + 8);
            bfrag[j][kt][0] = f2h2(w0.x, w0.y);
            bfrag[j][kt][1] = f2h2(w1.x, w1.y);
        }
    }

    // --- bias per gate for cols c0, c0+1 ---
    float bx[4], by[4];
#pragma unroll
    for (int j = 0; j < 4; j++) {
        bx[j] = bih[j * 128 + c0]     + bhh[j * 128 + c0];
        by[j] = bih[j * 128 + c0 + 1] + bhh[j * 128 + c0 + 1];
    }

    const int lr = tid >> 4;           // 0..31
    const int lc = (tid & 15) * 8;     // 0..120
    const size_t m_base = (size_t)blockIdx.x * 256;

    const int lm_row = lane & 15;
    const int lm_col = (lane >> 4) * 8;

    // prefetch subtile 0
    float4 v0 = *reinterpret_cast<const float4*>(x + (m_base + lr) * IDIM + lc);
    float4 v1 = *reinterpret_cast<const float4*>(x + (m_base + lr) * IDIM + lc + 4);

#pragma unroll 1
    for (int s = 0; s < 8; s++) {
        const int buf = s & 1;
        {
            __half2* sp = reinterpret_cast<__half2*>(&Ash[buf][lr][lc]);
            sp[0] = __floats2half2_rn(v0.x, v0.y);
            sp[1] = __floats2half2_rn(v0.z, v0.w);
            sp[2] = __floats2half2_rn(v1.x, v1.y);
            sp[3] = __floats2half2_rn(v1.z, v1.w);
        }
        __syncthreads();

        if (s < 7) {
            const size_t mr = m_base + (s + 1) * 32 + lr;
            v0 = *reinterpret_cast<const float4*>(x + mr * IDIM + lc);
            v1 = *reinterpret_cast<const float4*>(x + mr * IDIM + lc + 4);
        }

        float acc[2][4][4];
#pragma unroll
        for (int mi = 0; mi < 2; mi++)
#pragma unroll
            for (int j = 0; j < 4; j++)
#pragma unroll
                for (int p = 0; p < 4; p++) acc[mi][j][p] = 0.0f;

#pragma unroll
        for (int kt = 0; kt < 8; kt++) {
#pragma unroll
            for (int mi = 0; mi < 2; mi++) {
                uint32_t a0, a1, a2, a3;
                uint32_t saddr = (uint32_t)__cvta_generic_to_shared(
                    &Ash[buf][mi * 16 + lm_row][kt * 16 + lm_col]);
                ldsm4(a0, a1, a2, a3, saddr);
#pragma unroll
                for (int j = 0; j < 4; j++)
                    mma16816(acc[mi][j], a0, a1, a2, a3, bfrag[j][kt][0], bfrag[j][kt][1]);
            }
        }

        const size_t m0 = m_base + s * 32;
#pragma unroll
        for (int mi = 0; mi < 2; mi++) {
#pragma unroll
            for (int half_ = 0; half_ < 2; half_++) {
                const size_t row = m0 + mi * 16 + r0 + half_ * 8;
                const int pa = half_ * 2;
                uint4 v;
                v.x = f2h2(acc[mi][0][pa]     + bx[0], acc[mi][1][pa]     + bx[1]);
                v.y = f2h2(acc[mi][2][pa]     + bx[2], acc[mi][3][pa]     + bx[3]);
                v.z = f2h2(acc[mi][0][pa + 1] + by[0], acc[mi][1][pa + 1] + by[1]);
                v.w = f2h2(acc[mi][2][pa + 1] + by[2], acc[mi][3][pa + 1] + by[3]);
                *reinterpret_cast<uint4*>(&g_XgH[(row * 128 + c0) * 4]) = v;
            }
        }
    }
}

// ---------------------------------------------------------------------------
// Phase 2: masked LSTM recurrence — transposed W-stationary GEMM with
// GATE-INTERLEAVED m16 tiles: warp w's tile0 rows = {i-gate hcols 8w..8w+7,
// f-gate same cols}, tile1 = {g-gate, o-gate}. A-frags are register-built so
// tile rows need not be contiguous in W_hh. All four gates for the warp's 8
// hcols land in the SAME warp's accumulators -> gate exchange is 8 intra-warp
// shuffles (no smem buffer, no extra barrier). ONE barrier per step.
// Grid 128 blocks x 4 batch rows, 512 threads (16 warps), 16 MMA/warp/step.
// ---------------------------------------------------------------------------
__global__ void __launch_bounds__(512, 1)
lstm_rec_kernel(const float* __restrict__ hc,
                const int*   __restrict__ is_init,
                const float* __restrict__ Whh,
                float* __restrict__ out)
{
    __shared__ __half hbuf[2][8][136];    // h state [n][k], rows 4..7 zero
    __shared__ float  msk[LSEQ][4];       // 8KB mask table

    const int tid  = threadIdx.x;
    const int warp = tid >> 5;
    const int lane = tid & 31;
    const int q    = lane & 3;
    const int r0   = lane >> 2;
    const int n0   = blockIdx.x * 4;

    // epilogue element ownership: 1 element per lane
    const int er   = lane >> 3;                 // batch row 0..3
    const int ec   = lane & 7;                  // col idx in warp
    const int col  = warp * 8 + ec;             // global hcol
    const int n    = n0 + er;
    const int srcLane = ec * 4 + (er >> 1);     // lane holding this element's gates
    const int par  = er & 1;                    // accumulator parity (n = 2q+par)

    // --- A-fragments (loaded once): tile mt rows 0-7 = gate 2mt, rows 8-15 =
    //     gate 2mt+1, both at hcols [8w, 8w+8).  k from lane q. ---
    uint32_t afrag[2][8][4];
#pragma unroll
    for (int mt = 0; mt < 2; mt++) {
        const float* wlo = Whh + (size_t)((2 * mt)     * 128 + warp * 8 + r0) * HDIM;
        const float* whi = Whh + (size_t)((2 * mt + 1) * 128 + warp * 8 + r0) * HDIM;
#pragma unroll
        for (int kt = 0; kt < 8; kt++) {
            const int k = kt * 16 + q * 2;
            float2 w00 = *reinterpret_cast<const float2*>(wlo + k);
            float2 w01 = *reinterpret_cast<const float2*>(wlo + k + 8);
            float2 w10 = *reinterpret_cast<const float2*>(whi + k);
            float2 w11 = *reinterpret_cast<const float2*>(whi + k + 8);
            afrag[mt][kt][0] = f2h2(w00.x, w00.y);   // row r0      (gate 2mt)
            afrag[mt][kt][1] = f2h2(w10.x, w10.y);   // row r0+8    (gate 2mt+1)
            afrag[mt][kt][2] = f2h2(w01.x, w01.y);
            afrag[mt][kt][3] = f2h2(w11.x, w11.y);
        }
    }

    // --- mask table + zero rows 4..7 of both h buffers ---
    for (int idx = tid; idx < LSEQ * 4; idx += 512) {
        const int t = idx >> 2, r = idx & 3;
        msk[t][r] = 1.0f - (float)is_init[(size_t)t * NBATCH + n0 + r];
    }
    for (int idx = tid; idx < 2 * 4 * 136; idx += 512) {
        const int b = idx / (4 * 136), rem = idx % (4 * 136);
        hbuf[b][4 + rem / 136][rem % 136] = __half(0);
    }
    __syncthreads();

    // --- init state (t=0 mask applied); each lane owns one element ---
    const float m0v = msk[0][er];
    float creg = hc[(size_t)n * 256 + 128 + col] * m0v;
    hbuf[0][er][col] = __float2half(hc[(size_t)n * 256 + col] * m0v);
    __syncthreads();

    // per-lane Xg pointer: 8B per (m, hcol)
    const uint2* xgp = reinterpret_cast<const uint2*>(g_XgH);
    uint2 xcur = __ldg(&xgp[(size_t)n * 128 + col]);     // t = 0

    // ldmatrix lane base for B-frags: matrix g = lane>>3 at k-col g*8,
    // row = lane&7; step p advances k by 32 (64 bytes).
    const int lmr = lane & 7;
    const int lmg = (lane >> 3) * 8;
    const uint32_t lmBase0 = (uint32_t)__cvta_generic_to_shared(&hbuf[0][lmr][lmg]);
    const uint32_t lmBase1 = (uint32_t)__cvta_generic_to_shared(&hbuf[1][lmr][lmg]);

    const size_t OUT_HC = (size_t)LSEQ * NBATCH * HDIM;

#pragma unroll 1
    for (int t = 0; t < LSEQ; t++) {
        // prefetch next step's Xg
        const int tn = (t < LSEQ - 1) ? t + 1 : t;
        uint2 xnext = __ldg(&xgp[((size_t)tn * NBATCH + n) * 128 + col]);

        // --- MMA: 2 gate-interleaved m16 tiles x 8 kt ---
        float acc[2][4];
#pragma unroll
        for (int mt = 0; mt < 2; mt++)
#pragma unroll
            for (int p = 0; p < 4; p++) acc[mt][p] = 0.0f;

        const uint32_t lb = (t & 1) ? lmBase1 : lmBase0;
#pragma unroll
        for (int p = 0; p < 4; p++) {
            uint32_t b0, b1, b2, b3;   // b-frags for kt=2p and 2p+1
            ldsm4(b0, b1, b2, b3, lb + p * 64);
#pragma unroll
            for (int mt = 0; mt < 2; mt++) {
                mma16816(acc[mt], afrag[mt][2*p][0],   afrag[mt][2*p][1],
                                  afrag[mt][2*p][2],   afrag[mt][2*p][3],   b0, b1);
                mma16816(acc[mt], afrag[mt][2*p+1][0], afrag[mt][2*p+1][1],
                                  afrag[mt][2*p+1][2], afrag[mt][2*p+1][3], b2, b3);
            }
        }
        // acc[0] = {i(n=2q), i(2q+1), f(2q), f(2q+1)} for hcol 8w+r0
        // acc[1] = {g(2q),  g(2q+1),  o(2q), o(2q+1)}

        // --- intra-warp gate redistribution: 1 element per lane ---
        const float iv0 = __shfl_sync(0xffffffffu, acc[0][0], srcLane);
        const float iv1 = __shfl_sync(0xffffffffu, acc[0][1], srcLane);
        const float fv0 = __shfl_sync(0xffffffffu, acc[0][2], srcLane);
        const float fv1 = __shfl_sync(0xffffffffu, acc[0][3], srcLane);
        const float gv0 = __shfl_sync(0xffffffffu, acc[1][0], srcLane);
        const float gv1 = __shfl_sync(0xffffffffu, acc[1][1], srcLane);
        const float ov0 = __shfl_sync(0xffffffffu, acc[1][2], srcLane);
        const float ov1 = __shfl_sync(0xffffffffu, acc[1][3], srcLane);

        const float gi = par ? iv1 : iv0;
        const float gf = par ? fv1 : fv0;
        const float gg = par ? gv1 : gv0;
        const float go = par ? ov1 : ov0;

        // --- epilogue (gate order i,f,g,o) ---
        const float2 x01 = __half22float2(*reinterpret_cast<__half2*>(&xcur.x));
        const float2 x23 = __half22float2(*reinterpret_cast<__half2*>(&xcur.y));

        const float i_ = sigf(gi + x01.x);
        const float f_ = sigf(gf + x01.y);
        const float g_ = tanh_fast(gg + x23.x);
        const float o_ = sigf(go + x23.y);
        const float cn = __fmaf_rn(f_, creg, i_ * g_);
        const float hv = o_ * tanh_fast(cn);

        const float mn = (t < LSEQ - 1) ? msk[t + 1][er] : 1.0f;
        creg = cn * mn;
        hbuf[(t + 1) & 1][er][col] = __float2half(hv * mn);

        out[((size_t)t * NBATCH + n) * HDIM + col] = hv;

        if (t == LSEQ - 1) {
            out[OUT_HC + (size_t)n * 256 + col]       = hv;
            out[OUT_HC + (size_t)n * 256 + 128 + col] = cn;
        }
        __syncthreads();   // h(t+1) visible to all warps
        xcur = xnext;
    }
}

// ---------------------------------------------------------------------------
extern "C" void kernel_launch(void* const* d_in, const int* in_sizes, int n_in,
                              void* d_out, int out_size)
{
    const float* input   = (const float*)d_in[0];  // [L,N,I] fp32
    const float* hc      = (const float*)d_in[1];  // [N,2H]  fp32
    const int*   is_init = (const int*)  d_in[2];  // [L,N]   int32
    const float* Wih     = (const float*)d_in[3];  // [4H,I]
    const float* Whh     = (const float*)d_in[4];  // [4H,H]
    const float* bih     = (const float*)d_in[5];  // [4H]
    const float* bhh     = (const float*)d_in[6];  // [4H]
    float* out = (float*)d_out;                    // [L,N,H] then [N,2H]

    pregemm_kernel<<<(LSEQ * NBATCH) / 256, 512>>>(input, Wih, bih, bhh);
    lstm_rec_kernel<<<NBATCH / 4, 512>>>(hc, is_init, Whh, out);
}

// round 7
// speedup vs baseline: 1.0745x; 1.0745x over previous
#include <cuda_runtime.h>
#include <cuda_fp16.h>
#include <cstdint>
#include <cstddef>

#define LSEQ 512
#define NBATCH 512
#define IDIM 128
#define HDIM 128
#define GDIM 512   // 4*H

// Scratch: packed fp16 pre-activation input gates.
// Layout: [m = t*N+n][hcol 0..127][gate 0..3]  -> 8 bytes per (m, hcol)
// Padded by 2 steps so prefetch t+2 never needs a bounds check.
__device__ __half g_XgH[(size_t)(LSEQ + 2) * NBATCH * GDIM];

// ---------------------------------------------------------------------------
// helpers
// ---------------------------------------------------------------------------
__device__ __forceinline__ uint32_t f2h2(float a, float b) {
    __half2 h = __floats2half2_rn(a, b);
    return *reinterpret_cast<uint32_t*>(&h);
}

__device__ __forceinline__ void mma16816(float* d,
    uint32_t a0, uint32_t a1, uint32_t a2, uint32_t a3,
    uint32_t b0, uint32_t b1)
{
    asm volatile(
        "mma.sync.aligned.m16n8k16.row.col.f32.f16.f16.f32 "
        "{%0,%1,%2,%3}, {%4,%5,%6,%7}, {%8,%9}, {%0,%1,%2,%3};\n"
        : "+f"(d[0]), "+f"(d[1]), "+f"(d[2]), "+f"(d[3])
        : "r"(a0), "r"(a1), "r"(a2), "r"(a3), "r"(b0), "r"(b1));
}

__device__ __forceinline__ void ldsm4(uint32_t& a0, uint32_t& a1,
                                      uint32_t& a2, uint32_t& a3, uint32_t saddr)
{
    asm volatile("ldmatrix.sync.aligned.m8n8.x4.shared.b16 {%0,%1,%2,%3}, [%4];"
                 : "=r"(a0), "=r"(a1), "=r"(a2), "=r"(a3) : "r"(saddr));
}

// hardware tanh (MUFU.TANH): 1 MUFU op
__device__ __forceinline__ float tanhg(float x) {
    float y; asm("tanh.approx.f32 %0, %1;" : "=f"(y) : "f"(x)); return y;
}
// sigmoid via tanh identity: 1 MUFU + 1 FMA
__device__ __forceinline__ float sigg(float x) {
    return __fmaf_rn(0.5f, tanhg(0.5f * x), 0.5f);
}

// ---------------------------------------------------------------------------
// Phase 1: Xg = x@W_ih^T + (b_ih+b_hh), packed fp16 [m][hcol][gate].
// (unchanged from R5 — 154us, ~64% of memory roofline)
// ---------------------------------------------------------------------------
__global__ void __launch_bounds__(512, 1)
pregemm_kernel(const float* __restrict__ x,
               const float* __restrict__ Wih,
               const float* __restrict__ bih,
               const float* __restrict__ bhh)
{
    __shared__ __half Ash[2][32][136];

    const int tid  = threadIdx.x;
    const int warp = tid >> 5;
    const int lane = tid & 31;
    const int q    = lane & 3;
    const int r0   = lane >> 2;
    const int c0   = warp * 8 + q * 2;

    uint32_t bfrag[4][8][2];
#pragma unroll
    for (int j = 0; j < 4; j++) {
        const float* wr = Wih + (size_t)(j * 128 + warp * 8 + r0) * IDIM;
#pragma unroll
        for (int kt = 0; kt < 8; kt++) {
            const int k = kt * 16 + q * 2;
            float2 w0 = *reinterpret_cast<const float2*>(wr + k);
            float2 w1 = *reinterpret_cast<const float2*>(wr + k + 8);
            bfrag[j][kt][0] = f2h2(w0.x, w0.y);
            bfrag[j][kt][1] = f2h2(w1.x, w1.y);
        }
    }

    float bx[4], by[4];
#pragma unroll
    for (int j = 0; j < 4; j++) {
        bx[j] = bih[j * 128 + c0]     + bhh[j * 128 + c0];
        by[j] = bih[j * 128 + c0 + 1] + bhh[j * 128 + c0 + 1];
    }

    const int lr = tid >> 4;
    const int lc = (tid & 15) * 8;
    const size_t m_base = (size_t)blockIdx.x * 256;

    const int lm_row = lane & 15;
    const int lm_col = (lane >> 4) * 8;

    float4 v0 = *reinterpret_cast<const float4*>(x + (m_base + lr) * IDIM + lc);
    float4 v1 = *reinterpret_cast<const float4*>(x + (m_base + lr) * IDIM + lc + 4);

#pragma unroll 1
    for (int s = 0; s < 8; s++) {
        const int buf = s & 1;
        {
            __half2* sp = reinterpret_cast<__half2*>(&Ash[buf][lr][lc]);
            sp[0] = __floats2half2_rn(v0.x, v0.y);
            sp[1] = __floats2half2_rn(v0.z, v0.w);
            sp[2] = __floats2half2_rn(v1.x, v1.y);
            sp[3] = __floats2half2_rn(v1.z, v1.w);
        }
        __syncthreads();

        if (s < 7) {
            const size_t mr = m_base + (s + 1) * 32 + lr;
            v0 = *reinterpret_cast<const float4*>(x + mr * IDIM + lc);
            v1 = *reinterpret_cast<const float4*>(x + mr * IDIM + lc + 4);
        }

        float acc[2][4][4];
#pragma unroll
        for (int mi = 0; mi < 2; mi++)
#pragma unroll
            for (int j = 0; j < 4; j++)
#pragma unroll
                for (int p = 0; p < 4; p++) acc[mi][j][p] = 0.0f;

#pragma unroll
        for (int kt = 0; kt < 8; kt++) {
#pragma unroll
            for (int mi = 0; mi < 2; mi++) {
                uint32_t a0, a1, a2, a3;
                uint32_t saddr = (uint32_t)__cvta_generic_to_shared(
                    &Ash[buf][mi * 16 + lm_row][kt * 16 + lm_col]);
                ldsm4(a0, a1, a2, a3, saddr);
#pragma unroll
                for (int j = 0; j < 4; j++)
                    mma16816(acc[mi][j], a0, a1, a2, a3, bfrag[j][kt][0], bfrag[j][kt][1]);
            }
        }

        const size_t m0 = m_base + s * 32;
#pragma unroll
        for (int mi = 0; mi < 2; mi++) {
#pragma unroll
            for (int half_ = 0; half_ < 2; half_++) {
                const size_t row = m0 + mi * 16 + r0 + half_ * 8;
                const int pa = half_ * 2;
                uint4 v;
                v.x = f2h2(acc[mi][0][pa]     + bx[0], acc[mi][1][pa]     + bx[1]);
                v.y = f2h2(acc[mi][2][pa]     + bx[2], acc[mi][3][pa]     + bx[3]);
                v.z = f2h2(acc[mi][0][pa + 1] + by[0], acc[mi][1][pa + 1] + by[1]);
                v.w = f2h2(acc[mi][2][pa + 1] + by[2], acc[mi][3][pa + 1] + by[3]);
                *reinterpret_cast<uint4*>(&g_XgH[(row * 128 + c0) * 4]) = v;
            }
        }
    }
}

// ---------------------------------------------------------------------------
// Phase 2: masked LSTM recurrence (R5 structure: transposed W-stationary GEMM,
// gsh gate exchange, 2 barriers/step) with two changes:
//  (a) Xg folded into MMA accumulator init via a double-buffered gshX staging
//      buffer, filled by consumer lanes one step ahead (off critical path).
//  (b) activations via MUFU.TANH: 5 MUFU/element instead of 10.
// Grid 128 blocks x 4 batch rows, 512 threads (16 warps), 16 MMA/warp/step.
// ---------------------------------------------------------------------------
__global__ void __launch_bounds__(512, 1)
lstm_rec_kernel(const float* __restrict__ hc,
                const int*   __restrict__ is_init,
                const float* __restrict__ Whh,
                float* __restrict__ out)
{
    __shared__ __half hbuf[2][8][136];    // h state [n][k], rows 4..7 zero
    __shared__ float  gsh[GDIM][4];       // gate preacts out of MMA (8KB)
    __shared__ float  gshX[2][GDIM][6];   // Xg staged as [grow][n] (24KB, padded)
    __shared__ float  msk[LSEQ][4];       // mask table (8KB)

    const int tid  = threadIdx.x;
    const int warp = tid >> 5;
    const int lane = tid & 31;
    const int q    = lane & 3;
    const int r0   = lane >> 2;
    const int n0   = blockIdx.x * 4;

    // consumer element ownership: 1 element per lane
    const int er   = lane >> 3;                 // batch row 0..3
    const int ec   = lane & 7;                  // col idx in warp
    const int col  = warp * 8 + ec;             // global hcol
    const int n    = n0 + er;

    // --- A-fragments: W_hh gate rows [32w, 32w+32), loaded once ---
    uint32_t afrag[2][8][4];
#pragma unroll
    for (int mt = 0; mt < 2; mt++) {
        const int grow = warp * 32 + mt * 16 + r0;
#pragma unroll
        for (int kt = 0; kt < 8; kt++) {
            const int k = kt * 16 + q * 2;
            float2 w00 = *reinterpret_cast<const float2*>(Whh + (size_t)grow * HDIM + k);
            float2 w01 = *reinterpret_cast<const float2*>(Whh + (size_t)grow * HDIM + k + 8);
            float2 w10 = *reinterpret_cast<const float2*>(Whh + (size_t)(grow + 8) * HDIM + k);
            float2 w11 = *reinterpret_cast<const float2*>(Whh + (size_t)(grow + 8) * HDIM + k + 8);
            afrag[mt][kt][0] = f2h2(w00.x, w00.y);
            afrag[mt][kt][1] = f2h2(w10.x, w10.y);
            afrag[mt][kt][2] = f2h2(w01.x, w01.y);
            afrag[mt][kt][3] = f2h2(w11.x, w11.y);
        }
    }

    // --- mask table + zero rows 4..7 of both h buffers ---
    for (int idx = tid; idx < LSEQ * 4; idx += 512) {
        const int t = idx >> 2, r = idx & 3;
        msk[t][r] = 1.0f - (float)is_init[(size_t)t * NBATCH + n0 + r];
    }
    for (int idx = tid; idx < 2 * 4 * 136; idx += 512) {
        const int b = idx / (4 * 136), rem = idx % (4 * 136);
        hbuf[b][4 + rem / 136][rem % 136] = __half(0);
    }
    __syncthreads();

    // --- init state (t=0 mask applied); each lane owns one element ---
    const float m0v = msk[0][er];
    float creg = hc[(size_t)n * 256 + 128 + col] * m0v;
    hbuf[0][er][col] = __float2half(hc[(size_t)n * 256 + col] * m0v);

    // --- Xg staging: fill gshX[0] with t=0; prefetch t=1 into regs ---
    const uint2* xgp = reinterpret_cast<const uint2*>(g_XgH);
    {
        uint2 x0 = __ldg(&xgp[(size_t)n * 128 + col]);
        const float2 a01 = __half22float2(*reinterpret_cast<__half2*>(&x0.x));
        const float2 a23 = __half22float2(*reinterpret_cast<__half2*>(&x0.y));
        gshX[0][col][er]       = a01.x;   // i
        gshX[0][128 + col][er] = a01.y;   // f
        gshX[0][256 + col][er] = a23.x;   // g
        gshX[0][384 + col][er] = a23.y;   // o
    }
    uint2 xn1 = __ldg(&xgp[((size_t)1 * NBATCH + n) * 128 + col]);
    __syncthreads();

    // producer acc-init addressing (q<2 lanes hold valid n = 2q, 2q+1)
    const bool qlo = (q < 2);
    const int gbase = warp * 32 + r0;

    const int lmr = lane & 7;
    const int lmg = (lane >> 3) * 8;
    const uint32_t lmBase0 = (uint32_t)__cvta_generic_to_shared(&hbuf[0][lmr][lmg]);
    const uint32_t lmBase1 = (uint32_t)__cvta_generic_to_shared(&hbuf[1][lmr][lmg]);

    const size_t OUT_HC = (size_t)LSEQ * NBATCH * HDIM;

#pragma unroll 1
    for (int t = 0; t < LSEQ; t++) {
        // prefetch Xg(t+2) (array padded; garbage past the end is never consumed)
        uint2 xn2 = __ldg(&xgp[((size_t)(t + 2) * NBATCH + n) * 128 + col]);

        // --- MMA: acc initialized from gshX[t&1] (gates := Xg + h@W_hh^T) ---
        float acc[2][4];
        if (qlo) {
#pragma unroll
            for (int mt = 0; mt < 2; mt++) {
                const float2 lo = *reinterpret_cast<const float2*>(&gshX[t & 1][gbase + mt * 16][2 * q]);
                const float2 hi = *reinterpret_cast<const float2*>(&gshX[t & 1][gbase + mt * 16 + 8][2 * q]);
                acc[mt][0] = lo.x; acc[mt][1] = lo.y;
                acc[mt][2] = hi.x; acc[mt][3] = hi.y;
            }
        } else {
#pragma unroll
            for (int mt = 0; mt < 2; mt++)
#pragma unroll
                for (int p = 0; p < 4; p++) acc[mt][p] = 0.0f;
        }

        const uint32_t lb = (t & 1) ? lmBase1 : lmBase0;
#pragma unroll
        for (int p = 0; p < 4; p++) {
            uint32_t b0, b1, b2, b3;
            ldsm4(b0, b1, b2, b3, lb + p * 64);
#pragma unroll
            for (int mt = 0; mt < 2; mt++) {
                mma16816(acc[mt], afrag[mt][2*p][0],   afrag[mt][2*p][1],
                                  afrag[mt][2*p][2],   afrag[mt][2*p][3],   b0, b1);
                mma16816(acc[mt], afrag[mt][2*p+1][0], afrag[mt][2*p+1][1],
                                  afrag[mt][2*p+1][2], afrag[mt][2*p+1][3], b2, b3);
            }
        }

        // --- stage complete gate pre-acts (Xg already folded in) ---
        if (qlo) {
#pragma unroll
            for (int mt = 0; mt < 2; mt++) {
                *reinterpret_cast<float2*>(&gsh[gbase + mt * 16][2 * q]) =
                    make_float2(acc[mt][0], acc[mt][1]);
                *reinterpret_cast<float2*>(&gsh[gbase + mt * 16 + 8][2 * q]) =
                    make_float2(acc[mt][2], acc[mt][3]);
            }
        }
        __syncthreads();   // bar1: gates visible

        // --- stage Xg(t+1) into gshX[(t+1)&1] (off critical path) ---
        {
            const float2 a01 = __half22float2(*reinterpret_cast<__half2*>(&xn1.x));
            const float2 a23 = __half22float2(*reinterpret_cast<__half2*>(&xn1.y));
            const int b = (t + 1) & 1;
            gshX[b][col][er]       = a01.x;
            gshX[b][128 + col][er] = a01.y;
            gshX[b][256 + col][er] = a23.x;
            gshX[b][384 + col][er] = a23.y;
        }

        // --- epilogue: 1 element per lane (gate order i,f,g,o) ---
        const float i_ = sigg(gsh[col][er]);
        const float f_ = sigg(gsh[128 + col][er]);
        const float g_ = tanhg(gsh[256 + col][er]);
        const float o_ = sigg(gsh[384 + col][er]);
        const float cn = __fmaf_rn(f_, creg, i_ * g_);
        const float hv = o_ * tanhg(cn);

        const float mn = (t < LSEQ - 1) ? msk[t + 1][er] : 1.0f;
        creg = cn * mn;
        hbuf[(t + 1) & 1][er][col] = __float2half(hv * mn);

        out[((size_t)t * NBATCH + n) * HDIM + col] = hv;

        if (t == LSEQ - 1) {
            out[OUT_HC + (size_t)n * 256 + col]       = hv;
            out[OUT_HC + (size_t)n * 256 + 128 + col] = cn;
        }
        __syncthreads();   // bar2: h(t+1) + gshX visible
        xn1 = xn2;
    }
}

// ---------------------------------------------------------------------------
extern "C" void kernel_launch(void* const* d_in, const int* in_sizes, int n_in,
                              void* d_out, int out_size)
{
    const float* input   = (const float*)d_in[0];  // [L,N,I] fp32
    const float* hc      = (const float*)d_in[1];  // [N,2H]  fp32
    const int*   is_init = (const int*)  d_in[2];  // [L,N]   int32
    const float* Wih     = (const float*)d_in[3];  // [4H,I]
    const float* Whh     = (const float*)d_in[4];  // [4H,H]
    const float* bih     = (const float*)d_in[5];  // [4H]
    const float* bhh     = (const float*)d_in[6];  // [4H]
    float* out = (float*)d_out;                    // [L,N,H] then [N,2H]

    pregemm_kernel<<<(LSEQ * NBATCH) / 256, 512>>>(input, Wih, bih, bhh);
    lstm_rec_kernel<<<NBATCH / 4, 512>>>(hc, is_init, Whh, out);
}

// round 8
// speedup vs baseline: 1.1434x; 1.0641x over previous
#include <cuda_runtime.h>
#include <cuda_fp16.h>
#include <cstdint>
#include <cstddef>

#define LSEQ 512
#define NBATCH 512
#define IDIM 128
#define HDIM 128
#define GDIM 512   // 4*H

// Scratch: packed fp16 pre-activation input gates.
// Layout: [m = t*N+n][hcol 0..127][gate 0..3]  -> 8 bytes per (m, hcol)
__device__ __half g_XgH[(size_t)LSEQ * NBATCH * GDIM];

// ---------------------------------------------------------------------------
// helpers
// ---------------------------------------------------------------------------
__device__ __forceinline__ uint32_t f2h2(float a, float b) {
    __half2 h = __floats2half2_rn(a, b);
    return *reinterpret_cast<uint32_t*>(&h);
}

__device__ __forceinline__ void mma16816(float* d,
    uint32_t a0, uint32_t a1, uint32_t a2, uint32_t a3,
    uint32_t b0, uint32_t b1)
{
    asm volatile(
        "mma.sync.aligned.m16n8k16.row.col.f32.f16.f16.f32 "
        "{%0,%1,%2,%3}, {%4,%5,%6,%7}, {%8,%9}, {%0,%1,%2,%3};\n"
        : "+f"(d[0]), "+f"(d[1]), "+f"(d[2]), "+f"(d[3])
        : "r"(a0), "r"(a1), "r"(a2), "r"(a3), "r"(b0), "r"(b1));
}

__device__ __forceinline__ void ldsm4(uint32_t& a0, uint32_t& a1,
                                      uint32_t& a2, uint32_t& a3, uint32_t saddr)
{
    asm volatile("ldmatrix.sync.aligned.m8n8.x4.shared.b16 {%0,%1,%2,%3}, [%4];"
                 : "=r"(a0), "=r"(a1), "=r"(a2), "=r"(a3) : "r"(saddr));
}

// hardware tanh (MUFU.TANH): 1 MUFU op
__device__ __forceinline__ float tanhg(float x) {
    float y; asm("tanh.approx.f32 %0, %1;" : "=f"(y) : "f"(x)); return y;
}
// sigmoid via tanh identity: 1 MUFU + 1 FMA
__device__ __forceinline__ float sigg(float x) {
    return __fmaf_rn(0.5f, tanhg(0.5f * x), 0.5f);
}

// ---------------------------------------------------------------------------
// Phase 1: Xg = x@W_ih^T + (b_ih+b_hh), packed fp16 [m][hcol][gate].
// (unchanged from R5 — 154us)
// ---------------------------------------------------------------------------
__global__ void __launch_bounds__(512, 1)
pregemm_kernel(const float* __restrict__ x,
               const float* __restrict__ Wih,
               const float* __restrict__ bih,
               const float* __restrict__ bhh)
{
    __shared__ __half Ash[2][32][136];

    const int tid  = threadIdx.x;
    const int warp = tid >> 5;
    const int lane = tid & 31;
    const int q    = lane & 3;
    const int r0   = lane >> 2;
    const int c0   = warp * 8 + q * 2;

    uint32_t bfrag[4][8][2];
#pragma unroll
    for (int j = 0; j < 4; j++) {
        const float* wr = Wih + (size_t)(j * 128 + warp * 8 + r0) * IDIM;
#pragma unroll
        for (int kt = 0; kt < 8; kt++) {
            const int k = kt * 16 + q * 2;
            float2 w0 = *reinterpret_cast<const float2*>(wr + k);
            float2 w1 = *reinterpret_cast<const float2*>(wr + k + 8);
            bfrag[j][kt][0] = f2h2(w0.x, w0.y);
            bfrag[j][kt][1] = f2h2(w1.x, w1.y);
        }
    }

    float bx[4], by[4];
#pragma unroll
    for (int j = 0; j < 4; j++) {
        bx[j] = bih[j * 128 + c0]     + bhh[j * 128 + c0];
        by[j] = bih[j * 128 + c0 + 1] + bhh[j * 128 + c0 + 1];
    }

    const int lr = tid >> 4;
    const int lc = (tid & 15) * 8;
    const size_t m_base = (size_t)blockIdx.x * 256;

    const int lm_row = lane & 15;
    const int lm_col = (lane >> 4) * 8;

    float4 v0 = *reinterpret_cast<const float4*>(x + (m_base + lr) * IDIM + lc);
    float4 v1 = *reinterpret_cast<const float4*>(x + (m_base + lr) * IDIM + lc + 4);

#pragma unroll 1
    for (int s = 0; s < 8; s++) {
        const int buf = s & 1;
        {
            __half2* sp = reinterpret_cast<__half2*>(&Ash[buf][lr][lc]);
            sp[0] = __floats2half2_rn(v0.x, v0.y);
            sp[1] = __floats2half2_rn(v0.z, v0.w);
            sp[2] = __floats2half2_rn(v1.x, v1.y);
            sp[3] = __floats2half2_rn(v1.z, v1.w);
        }
        __syncthreads();

        if (s < 7) {
            const size_t mr = m_base + (s + 1) * 32 + lr;
            v0 = *reinterpret_cast<const float4*>(x + mr * IDIM + lc);
            v1 = *reinterpret_cast<const float4*>(x + mr * IDIM + lc + 4);
        }

        float acc[2][4][4];
#pragma unroll
        for (int mi = 0; mi < 2; mi++)
#pragma unroll
            for (int j = 0; j < 4; j++)
#pragma unroll
                for (int p = 0; p < 4; p++) acc[mi][j][p] = 0.0f;

#pragma unroll
        for (int kt = 0; kt < 8; kt++) {
#pragma unroll
            for (int mi = 0; mi < 2; mi++) {
                uint32_t a0, a1, a2, a3;
                uint32_t saddr = (uint32_t)__cvta_generic_to_shared(
                    &Ash[buf][mi * 16 + lm_row][kt * 16 + lm_col]);
                ldsm4(a0, a1, a2, a3, saddr);
#pragma unroll
                for (int j = 0; j < 4; j++)
                    mma16816(acc[mi][j], a0, a1, a2, a3, bfrag[j][kt][0], bfrag[j][kt][1]);
            }
        }

        const size_t m0 = m_base + s * 32;
#pragma unroll
        for (int mi = 0; mi < 2; mi++) {
#pragma unroll
            for (int half_ = 0; half_ < 2; half_++) {
                const size_t row = m0 + mi * 16 + r0 + half_ * 8;
                const int pa = half_ * 2;
                uint4 v;
                v.x = f2h2(acc[mi][0][pa]     + bx[0], acc[mi][1][pa]     + bx[1]);
                v.y = f2h2(acc[mi][2][pa]     + bx[2], acc[mi][3][pa]     + bx[3]);
                v.z = f2h2(acc[mi][0][pa + 1] + by[0], acc[mi][1][pa + 1] + by[1]);
                v.w = f2h2(acc[mi][2][pa + 1] + by[2], acc[mi][3][pa + 1] + by[3]);
                *reinterpret_cast<uint4*>(&g_XgH[(row * 128 + c0) * 4]) = v;
            }
        }
    }
}

// ---------------------------------------------------------------------------
// Phase 2: masked LSTM recurrence — transposed W-stationary GEMM with
// PRE-FRAGMENTED B operand:
//   bbuf[buf][kt][l16] (uint2) = { h2[n][k0], h2[n][k0+8] },
//   n = l16>>2, k0 = kt*16 + (l16&3)*2.
// Each warp fetches its per-kt B pair with ONE LDS.64 (lanes 16-31 read the
// same 128B -> broadcast; their garbage B only feeds discarded C columns
// n>=4). Epilogue lanes write next h directly into fragment slots (STS.16).
// No ldmatrix, no hbuf, no zero padding. Xg added in epilogue (gshX removed).
// Grid 128 blocks x 4 batch rows, 512 threads, 16 MMA/warp/step, 2 barriers.
// ---------------------------------------------------------------------------
__global__ void __launch_bounds__(512, 1)
lstm_rec_kernel(const float* __restrict__ hc,
                const int*   __restrict__ is_init,
                const float* __restrict__ Whh,
                float* __restrict__ out)
{
    __shared__ uint2 bbuf[2][8][16];      // pre-fragmented h (2KB)
    __shared__ float gsh[GDIM][4];        // gate preacts exchange (8KB)
    __shared__ float msk[LSEQ][4];        // mask table (8KB)

    const int tid  = threadIdx.x;
    const int warp = tid >> 5;
    const int lane = tid & 31;
    const int q    = lane & 3;
    const int r0   = lane >> 2;
    const int n0   = blockIdx.x * 4;

    // epilogue element ownership: 1 element per lane
    const int er   = lane >> 3;                 // batch row 0..3
    const int ec   = lane & 7;                  // col idx in warp
    const int col  = warp * 8 + ec;             // global hcol
    const int n    = n0 + er;

    // fragment-slot address for this lane's h element:
    // kt = col>>4, r = col&15; r<8 -> .x half2, else .y; qq = (r&7)>>1
    const int fkt  = col >> 4;
    const int fr   = col & 15;
    const int fl16 = er * 4 + ((fr & 7) >> 1);
    const uint32_t fragOff = (uint32_t)(((fkt * 16 + fl16) * 8) +
                                        ((fr & 8) ? 4 : 0) + (col & 1) * 2);
    const uint32_t bbufBase0 = (uint32_t)__cvta_generic_to_shared(&bbuf[0][0][0]);
    const uint32_t bbufBase1 = (uint32_t)__cvta_generic_to_shared(&bbuf[1][0][0]);

    // --- A-fragments: W_hh gate rows [32w, 32w+32), loaded once ---
    uint32_t afrag[2][8][4];
#pragma unroll
    for (int mt = 0; mt < 2; mt++) {
        const int grow = warp * 32 + mt * 16 + r0;
#pragma unroll
        for (int kt = 0; kt < 8; kt++) {
            const int k = kt * 16 + q * 2;
            float2 w00 = *reinterpret_cast<const float2*>(Whh + (size_t)grow * HDIM + k);
            float2 w01 = *reinterpret_cast<const float2*>(Whh + (size_t)grow * HDIM + k + 8);
            float2 w10 = *reinterpret_cast<const float2*>(Whh + (size_t)(grow + 8) * HDIM + k);
            float2 w11 = *reinterpret_cast<const float2*>(Whh + (size_t)(grow + 8) * HDIM + k + 8);
            afrag[mt][kt][0] = f2h2(w00.x, w00.y);
            afrag[mt][kt][1] = f2h2(w10.x, w10.y);
            afrag[mt][kt][2] = f2h2(w01.x, w01.y);
            afrag[mt][kt][3] = f2h2(w11.x, w11.y);
        }
    }

    // --- mask table ---
    for (int idx = tid; idx < LSEQ * 4; idx += 512) {
        const int t = idx >> 2, r = idx & 3;
        msk[t][r] = 1.0f - (float)is_init[(size_t)t * NBATCH + n0 + r];
    }
    __syncthreads();

    // --- init state (t=0 mask applied); write h0 into fragment slots ---
    const float m0v = msk[0][er];
    float creg = hc[(size_t)n * 256 + 128 + col] * m0v;
    {
        const __half h0 = __float2half(hc[(size_t)n * 256 + col] * m0v);
        const uint16_t hb = *reinterpret_cast<const uint16_t*>(&h0);
        asm volatile("st.shared.u16 [%0], %1;" :: "r"(bbufBase0 + fragOff), "h"(hb));
    }
    __syncthreads();

    // per-lane Xg pointer: 8B per (m, hcol)
    const uint2* xgp = reinterpret_cast<const uint2*>(g_XgH);
    uint2 xcur = __ldg(&xgp[(size_t)n * 128 + col]);     // t = 0

    // B-fragment read address: one LDS.64 per kt, lane&15 slot (16-31 broadcast)
    const uint32_t bRead0 = bbufBase0 + (uint32_t)(lane & 15) * 8;
    const uint32_t bRead1 = bbufBase1 + (uint32_t)(lane & 15) * 8;

    // gsh producer addressing (q<2 lanes hold valid n = 2q, 2q+1)
    const bool qlo = (q < 2);
    const int gbase = warp * 32 + r0;

    const size_t OUT_HC = (size_t)LSEQ * NBATCH * HDIM;

#pragma unroll 1
    for (int t = 0; t < LSEQ; t++) {
        // prefetch next step's Xg
        const int tn = (t < LSEQ - 1) ? t + 1 : t;
        uint2 xnext = __ldg(&xgp[((size_t)tn * NBATCH + n) * 128 + col]);

        // --- MMA: 2 m16 tiles x 8 kt; B via one LDS.64 per kt ---
        float acc[2][4];
#pragma unroll
        for (int mt = 0; mt < 2; mt++)
#pragma unroll
            for (int p = 0; p < 4; p++) acc[mt][p] = 0.0f;

        const uint32_t brd = (t & 1) ? bRead1 : bRead0;
#pragma unroll
        for (int kt = 0; kt < 8; kt++) {
            uint32_t b0, b1;
            asm volatile("ld.shared.v2.u32 {%0,%1}, [%2];"
                         : "=r"(b0), "=r"(b1) : "r"(brd + kt * 128));
#pragma unroll
            for (int mt = 0; mt < 2; mt++)
                mma16816(acc[mt], afrag[mt][kt][0], afrag[mt][kt][1],
                                  afrag[mt][kt][2], afrag[mt][kt][3], b0, b1);
        }

        // --- stage gate pre-acts: gsh[grow][n] ---
        if (qlo) {
#pragma unroll
            for (int mt = 0; mt < 2; mt++) {
                *reinterpret_cast<float2*>(&gsh[gbase + mt * 16][2 * q]) =
                    make_float2(acc[mt][0], acc[mt][1]);
                *reinterpret_cast<float2*>(&gsh[gbase + mt * 16 + 8][2 * q]) =
                    make_float2(acc[mt][2], acc[mt][3]);
            }
        }
        __syncthreads();   // bar1: gates visible

        // --- epilogue: 1 element per lane (gate order i,f,g,o) ---
        const float2 x01 = __half22float2(*reinterpret_cast<__half2*>(&xcur.x));
        const float2 x23 = __half22float2(*reinterpret_cast<__half2*>(&xcur.y));

        const float i_ = sigg(gsh[col][er]        + x01.x);
        const float f_ = sigg(gsh[128 + col][er]  + x01.y);
        const float g_ = tanhg(gsh[256 + col][er] + x23.x);
        const float o_ = sigg(gsh[384 + col][er]  + x23.y);
        const float cn = __fmaf_rn(f_, creg, i_ * g_);
        const float hv = o_ * tanhg(cn);

        const float mn = (t < LSEQ - 1) ? msk[t + 1][er] : 1.0f;
        creg = cn * mn;

        // write next-step h directly into its fragment slot
        {
            const __half hm = __float2half(hv * mn);
            const uint16_t hb = *reinterpret_cast<const uint16_t*>(&hm);
            const uint32_t dst = ((t + 1) & 1) ? bbufBase1 : bbufBase0;
            asm volatile("st.shared.u16 [%0], %1;" :: "r"(dst + fragOff), "h"(hb));
        }

        out[((size_t)t * NBATCH + n) * HDIM + col] = hv;

        if (t == LSEQ - 1) {
            out[OUT_HC + (size_t)n * 256 + col]       = hv;
            out[OUT_HC + (size_t)n * 256 + 128 + col] = cn;
        }
        __syncthreads();   // bar2: bbuf(t+1) visible
        xcur = xnext;
    }
}

// ---------------------------------------------------------------------------
extern "C" void kernel_launch(void* const* d_in, const int* in_sizes, int n_in,
                              void* d_out, int out_size)
{
    const float* input   = (const float*)d_in[0];  // [L,N,I] fp32
    const float* hc      = (const float*)d_in[1];  // [N,2H]  fp32
    const int*   is_init = (const int*)  d_in[2];  // [L,N]   int32
    const float* Wih     = (const float*)d_in[3];  // [4H,I]
    const float* Whh     = (const float*)d_in[4];  // [4H,H]
    const float* bih     = (const float*)d_in[5];  // [4H]
    const float* bhh     = (const float*)d_in[6];  // [4H]
    float* out = (float*)d_out;                    // [L,N,H] then [N,2H]

    pregemm_kernel<<<(LSEQ * NBATCH) / 256, 512>>>(input, Wih, bih, bhh);
    lstm_rec_kernel<<<NBATCH / 4, 512>>>(hc, is_init, Whh, out);
}

// round 9
// speedup vs baseline: 1.2168x; 1.0642x over previous
#include <cuda_runtime.h>
#include <cuda_fp16.h>
#include <cstdint>
#include <cstddef>

#define LSEQ 512
#define NBATCH 512
#define IDIM 128
#define HDIM 128
#define GDIM 512   // 4*H

// Scratch: packed fp16 pre-activation input gates.
// Layout: [m = t*N+n][hcol 0..127][gate 0..3]  -> 8 bytes per (m, hcol)
// Padded by 1 step so the t+1 prefetch needs no bounds check.
__device__ __half g_XgH[(size_t)(LSEQ + 1) * NBATCH * GDIM];

// ---------------------------------------------------------------------------
// helpers
// ---------------------------------------------------------------------------
__device__ __forceinline__ uint32_t f2h2(float a, float b) {
    __half2 h = __floats2half2_rn(a, b);
    return *reinterpret_cast<uint32_t*>(&h);
}

__device__ __forceinline__ void mma16816(float* d,
    uint32_t a0, uint32_t a1, uint32_t a2, uint32_t a3,
    uint32_t b0, uint32_t b1)
{
    asm volatile(
        "mma.sync.aligned.m16n8k16.row.col.f32.f16.f16.f32 "
        "{%0,%1,%2,%3}, {%4,%5,%6,%7}, {%8,%9}, {%0,%1,%2,%3};\n"
        : "+f"(d[0]), "+f"(d[1]), "+f"(d[2]), "+f"(d[3])
        : "r"(a0), "r"(a1), "r"(a2), "r"(a3), "r"(b0), "r"(b1));
}

__device__ __forceinline__ void ldsm4(uint32_t& a0, uint32_t& a1,
                                      uint32_t& a2, uint32_t& a3, uint32_t saddr)
{
    asm volatile("ldmatrix.sync.aligned.m8n8.x4.shared.b16 {%0,%1,%2,%3}, [%4];"
                 : "=r"(a0), "=r"(a1), "=r"(a2), "=r"(a3) : "r"(saddr));
}

// hardware tanh (MUFU.TANH): 1 MUFU op
__device__ __forceinline__ float tanhg(float x) {
    float y; asm("tanh.approx.f32 %0, %1;" : "=f"(y) : "f"(x)); return y;
}
// sigmoid via tanh identity: 1 MUFU + 1 FMA
__device__ __forceinline__ float sigg(float x) {
    return __fmaf_rn(0.5f, tanhg(0.5f * x), 0.5f);
}

// ---------------------------------------------------------------------------
// Phase 1: Xg = x@W_ih^T + (b_ih+b_hh), packed fp16 [m][hcol][gate].
// (unchanged from R5 — 154us)
// ---------------------------------------------------------------------------
__global__ void __launch_bounds__(512, 1)
pregemm_kernel(const float* __restrict__ x,
               const float* __restrict__ Wih,
               const float* __restrict__ bih,
               const float* __restrict__ bhh)
{
    __shared__ __half Ash[2][32][136];

    const int tid  = threadIdx.x;
    const int warp = tid >> 5;
    const int lane = tid & 31;
    const int q    = lane & 3;
    const int r0   = lane >> 2;
    const int c0   = warp * 8 + q * 2;

    uint32_t bfrag[4][8][2];
#pragma unroll
    for (int j = 0; j < 4; j++) {
        const float* wr = Wih + (size_t)(j * 128 + warp * 8 + r0) * IDIM;
#pragma unroll
        for (int kt = 0; kt < 8; kt++) {
            const int k = kt * 16 + q * 2;
            float2 w0 = *reinterpret_cast<const float2*>(wr + k);
            float2 w1 = *reinterpret_cast<const float2*>(wr + k + 8);
            bfrag[j][kt][0] = f2h2(w0.x, w0.y);
            bfrag[j][kt][1] = f2h2(w1.x, w1.y);
        }
    }

    float bx[4], by[4];
#pragma unroll
    for (int j = 0; j < 4; j++) {
        bx[j] = bih[j * 128 + c0]     + bhh[j * 128 + c0];
        by[j] = bih[j * 128 + c0 + 1] + bhh[j * 128 + c0 + 1];
    }

    const int lr = tid >> 4;
    const int lc = (tid & 15) * 8;
    const size_t m_base = (size_t)blockIdx.x * 256;

    const int lm_row = lane & 15;
    const int lm_col = (lane >> 4) * 8;

    float4 v0 = *reinterpret_cast<const float4*>(x + (m_base + lr) * IDIM + lc);
    float4 v1 = *reinterpret_cast<const float4*>(x + (m_base + lr) * IDIM + lc + 4);

#pragma unroll 1
    for (int s = 0; s < 8; s++) {
        const int buf = s & 1;
        {
            __half2* sp = reinterpret_cast<__half2*>(&Ash[buf][lr][lc]);
            sp[0] = __floats2half2_rn(v0.x, v0.y);
            sp[1] = __floats2half2_rn(v0.z, v0.w);
            sp[2] = __floats2half2_rn(v1.x, v1.y);
            sp[3] = __floats2half2_rn(v1.z, v1.w);
        }
        __syncthreads();

        if (s < 7) {
            const size_t mr = m_base + (s + 1) * 32 + lr;
            v0 = *reinterpret_cast<const float4*>(x + mr * IDIM + lc);
            v1 = *reinterpret_cast<const float4*>(x + mr * IDIM + lc + 4);
        }

        float acc[2][4][4];
#pragma unroll
        for (int mi = 0; mi < 2; mi++)
#pragma unroll
            for (int j = 0; j < 4; j++)
#pragma unroll
                for (int p = 0; p < 4; p++) acc[mi][j][p] = 0.0f;

#pragma unroll
        for (int kt = 0; kt < 8; kt++) {
#pragma unroll
            for (int mi = 0; mi < 2; mi++) {
                uint32_t a0, a1, a2, a3;
                uint32_t saddr = (uint32_t)__cvta_generic_to_shared(
                    &Ash[buf][mi * 16 + lm_row][kt * 16 + lm_col]);
                ldsm4(a0, a1, a2, a3, saddr);
#pragma unroll
                for (int j = 0; j < 4; j++)
                    mma16816(acc[mi][j], a0, a1, a2, a3, bfrag[j][kt][0], bfrag[j][kt][1]);
            }
        }

        const size_t m0 = m_base + s * 32;
#pragma unroll
        for (int mi = 0; mi < 2; mi++) {
#pragma unroll
            for (int half_ = 0; half_ < 2; half_++) {
                const size_t row = m0 + mi * 16 + r0 + half_ * 8;
                const int pa = half_ * 2;
                uint4 v;
                v.x = f2h2(acc[mi][0][pa]     + bx[0], acc[mi][1][pa]     + bx[1]);
                v.y = f2h2(acc[mi][2][pa]     + bx[2], acc[mi][3][pa]     + bx[3]);
                v.z = f2h2(acc[mi][0][pa + 1] + by[0], acc[mi][1][pa + 1] + by[1]);
                v.w = f2h2(acc[mi][2][pa + 1] + by[2], acc[mi][3][pa + 1] + by[3]);
                *reinterpret_cast<uint4*>(&g_XgH[(row * 128 + c0) * 4]) = v;
            }
        }
    }
}

// ---------------------------------------------------------------------------
// Phase 2: masked LSTM recurrence — transposed W-stationary GEMM,
// pre-fragmented B operand (R8), GATE-INTERLEAVED m16 tiles (R6 mapping):
// warp w's tile0 = {i,f} gate rows at hcols [8w,8w+8), tile1 = {g,o}.
// Producer warp == consumer warp, so the gate exchange is WARP-PRIVATE:
// 4 STS.64 -> __syncwarp -> 4 LDS.32 into a 512B per-warp buffer. The
// block-wide bar1 is GONE; one __syncthreads per step (h publish only).
// HMMA accumulation split into two 4-deep chains to cut dep latency.
// Grid 128 blocks x 4 batch rows, 512 threads, 16 MMA/warp/step.
// ---------------------------------------------------------------------------
__global__ void __launch_bounds__(512, 1)
lstm_rec_kernel(const float* __restrict__ hc,
                const int*   __restrict__ is_init,
                const float* __restrict__ Whh,
                float* __restrict__ out)
{
    __shared__ uint2 bbuf[2][8][16];      // pre-fragmented h (2KB)
    __shared__ float gw[16][4][8][4];     // per-warp gate exchange (8KB)
    __shared__ float msk[LSEQ][4];        // mask table (8KB)

    const int tid  = threadIdx.x;
    const int warp = tid >> 5;
    const int lane = tid & 31;
    const int q    = lane & 3;
    const int r0   = lane >> 2;
    const int n0   = blockIdx.x * 4;

    // epilogue element ownership: 1 element per lane
    const int er   = lane >> 3;                 // batch row 0..3
    const int ec   = lane & 7;                  // col idx in warp
    const int col  = warp * 8 + ec;             // global hcol
    const int n    = n0 + er;

    // fragment-slot address for this lane's h element (bbuf layout):
    // bbuf[buf][kt][l16].{x,y} ; kt = col>>4, r = col&15
    const int fkt  = col >> 4;
    const int fr   = col & 15;
    const int fl16 = er * 4 + ((fr & 7) >> 1);
    const uint32_t fragOff = (uint32_t)(((fkt * 16 + fl16) * 8) +
                                        ((fr & 8) ? 4 : 0) + (col & 1) * 2);
    const uint32_t bbufBase0 = (uint32_t)__cvta_generic_to_shared(&bbuf[0][0][0]);
    const uint32_t bbufBase1 = (uint32_t)__cvta_generic_to_shared(&bbuf[1][0][0]);

    // --- A-fragments (gate-interleaved tiles), loaded once ---
    // tile mt: rows 0-7 = gate 2mt, rows 8-15 = gate 2mt+1, hcols [8w,8w+8)
    uint32_t afrag[2][8][4];
#pragma unroll
    for (int mt = 0; mt < 2; mt++) {
        const float* wlo = Whh + (size_t)((2 * mt)     * 128 + warp * 8 + r0) * HDIM;
        const float* whi = Whh + (size_t)((2 * mt + 1) * 128 + warp * 8 + r0) * HDIM;
#pragma unroll
        for (int kt = 0; kt < 8; kt++) {
            const int k = kt * 16 + q * 2;
            float2 w00 = *reinterpret_cast<const float2*>(wlo + k);
            float2 w01 = *reinterpret_cast<const float2*>(wlo + k + 8);
            float2 w10 = *reinterpret_cast<const float2*>(whi + k);
            float2 w11 = *reinterpret_cast<const float2*>(whi + k + 8);
            afrag[mt][kt][0] = f2h2(w00.x, w00.y);   // row r0     (gate 2mt)
            afrag[mt][kt][1] = f2h2(w10.x, w10.y);   // row r0+8   (gate 2mt+1)
            afrag[mt][kt][2] = f2h2(w01.x, w01.y);
            afrag[mt][kt][3] = f2h2(w11.x, w11.y);
        }
    }

    // --- mask table ---
    for (int idx = tid; idx < LSEQ * 4; idx += 512) {
        const int t = idx >> 2, r = idx & 3;
        msk[t][r] = 1.0f - (float)is_init[(size_t)t * NBATCH + n0 + r];
    }
    __syncthreads();

    // --- init state (t=0 mask applied); write h0 into fragment slots ---
    const float m0v = msk[0][er];
    float creg = hc[(size_t)n * 256 + 128 + col] * m0v;
    {
        const __half h0 = __float2half(hc[(size_t)n * 256 + col] * m0v);
        const uint16_t hb = *reinterpret_cast<const uint16_t*>(&h0);
        asm volatile("st.shared.u16 [%0], %1;" :: "r"(bbufBase0 + fragOff), "h"(hb));
    }
    __syncthreads();

    // per-lane Xg pointer: 8B per (m, hcol)
    const uint2* xgp = reinterpret_cast<const uint2*>(g_XgH);
    uint2 xcur = __ldg(&xgp[(size_t)n * 128 + col]);     // t = 0

    // B-fragment read address: one LDS.64 per kt, lane&15 slot (16-31 broadcast)
    const uint32_t bRead0 = bbufBase0 + (uint32_t)(lane & 15) * 8;
    const uint32_t bRead1 = bbufBase1 + (uint32_t)(lane & 15) * 8;

    const bool qlo = (q < 2);
    const size_t OUT_HC = (size_t)LSEQ * NBATCH * HDIM;

#pragma unroll 1
    for (int t = 0; t < LSEQ; t++) {
        // prefetch next step's Xg (array padded by 1 step)
        uint2 xnext = __ldg(&xgp[((size_t)(t + 1) * NBATCH + n) * 128 + col]);

        // --- MMA: 2 gate-interleaved m16 tiles x 8 kt, split acc chains ---
        float acc[2][4], accB[2][4];
#pragma unroll
        for (int mt = 0; mt < 2; mt++)
#pragma unroll
            for (int p = 0; p < 4; p++) { acc[mt][p] = 0.0f; accB[mt][p] = 0.0f; }

        const uint32_t brd = (t & 1) ? bRead1 : bRead0;
#pragma unroll
        for (int kt = 0; kt < 4; kt++) {
            uint32_t b0, b1, c0_, c1_;
            asm volatile("ld.shared.v2.u32 {%0,%1}, [%2];"
                         : "=r"(b0), "=r"(b1) : "r"(brd + kt * 128));
            asm volatile("ld.shared.v2.u32 {%0,%1}, [%2];"
                         : "=r"(c0_), "=r"(c1_) : "r"(brd + (kt + 4) * 128));
#pragma unroll
            for (int mt = 0; mt < 2; mt++) {
                mma16816(acc[mt],  afrag[mt][kt][0],     afrag[mt][kt][1],
                                   afrag[mt][kt][2],     afrag[mt][kt][3],     b0, b1);
                mma16816(accB[mt], afrag[mt][kt + 4][0], afrag[mt][kt + 4][1],
                                   afrag[mt][kt + 4][2], afrag[mt][kt + 4][3], c0_, c1_);
            }
        }
#pragma unroll
        for (int mt = 0; mt < 2; mt++)
#pragma unroll
            for (int p = 0; p < 4; p++) acc[mt][p] += accB[mt][p];

        // acc[0] = {i(n=2q), i(2q+1), f(2q), f(2q+1)} for hcol 8w+r0
        // acc[1] = {g(2q),  g(2q+1),  o(2q), o(2q+1)}

        // --- warp-private gate exchange (no block barrier) ---
        if (qlo) {
            *reinterpret_cast<float2*>(&gw[warp][0][r0][2 * q]) =
                make_float2(acc[0][0], acc[0][1]);   // i
            *reinterpret_cast<float2*>(&gw[warp][1][r0][2 * q]) =
                make_float2(acc[0][2], acc[0][3]);   // f
            *reinterpret_cast<float2*>(&gw[warp][2][r0][2 * q]) =
                make_float2(acc[1][0], acc[1][1]);   // g
            *reinterpret_cast<float2*>(&gw[warp][3][r0][2 * q]) =
                make_float2(acc[1][2], acc[1][3]);   // o
        }
        __syncwarp();

        // --- epilogue: 1 element per lane (gate order i,f,g,o) ---
        const float2 x01 = __half22float2(*reinterpret_cast<__half2*>(&xcur.x));
        const float2 x23 = __half22float2(*reinterpret_cast<__half2*>(&xcur.y));

        const float i_ = sigg(gw[warp][0][ec][er] + x01.x);
        const float f_ = sigg(gw[warp][1][ec][er] + x01.y);
        const float g_ = tanhg(gw[warp][2][ec][er] + x23.x);
        const float o_ = sigg(gw[warp][3][ec][er] + x23.y);
        const float cn = __fmaf_rn(f_, creg, i_ * g_);
        const float hv = o_ * tanhg(cn);

        out[((size_t)t * NBATCH + n) * HDIM + col] = hv;

        const float mn = (t < LSEQ - 1) ? msk[t + 1][er] : 1.0f;
        creg = cn * mn;

        // write next-step h directly into its fragment slot
        {
            const __half hm = __float2half(hv * mn);
            const uint16_t hb = *reinterpret_cast<const uint16_t*>(&hm);
            const uint32_t dst = ((t + 1) & 1) ? bbufBase1 : bbufBase0;
            asm volatile("st.shared.u16 [%0], %1;" :: "r"(dst + fragOff), "h"(hb));
        }

        if (t == LSEQ - 1) {
            out[OUT_HC + (size_t)n * 256 + col]       = hv;
            out[OUT_HC + (size_t)n * 256 + 128 + col] = cn;
        }
        __syncthreads();   // h(t+1) visible to all warps (only barrier per step)
        xcur = xnext;
    }
}

// ---------------------------------------------------------------------------
extern "C" void kernel_launch(void* const* d_in, const int* in_sizes, int n_in,
                              void* d_out, int out_size)
{
    const float* input   = (const float*)d_in[0];  // [L,N,I] fp32
    const float* hc      = (const float*)d_in[1];  // [N,2H]  fp32
    const int*   is_init = (const int*)  d_in[2];  // [L,N]   int32
    const float* Wih     = (const float*)d_in[3];  // [4H,I]
    const float* Whh     = (const float*)d_in[4];  // [4H,H]
    const float* bih     = (const float*)d_in[5];  // [4H]
    const float* bhh     = (const float*)d_in[6];  // [4H]
    float* out = (float*)d_out;                    // [L,N,H] then [N,2H]

    pregemm_kernel<<<(LSEQ * NBATCH) / 256, 512>>>(input, Wih, bih, bhh);
    lstm_rec_kernel<<<NBATCH / 4, 512>>>(hc, is_init, Whh, out);
}

// round 10
// speedup vs baseline: 1.2218x; 1.0042x over previous
#include <cuda_runtime.h>
#include <cuda_fp16.h>
#include <cstdint>
#include <cstddef>

#define LSEQ 512
#define NBATCH 512
#define IDIM 128
#define HDIM 128
#define GDIM 512   // 4*H

// Scratch: packed fp16 pre-activation input gates.
// Layout: [m = t*N+n][hcol 0..127][gate 0..3]  -> 8 bytes per (m, hcol)
// Padded by 1 step so the t+1 prefetch needs no bounds check.
__device__ __half g_XgH[(size_t)(LSEQ + 1) * NBATCH * GDIM];

// ---------------------------------------------------------------------------
// helpers
// ---------------------------------------------------------------------------
__device__ __forceinline__ uint32_t f2h2(float a, float b) {
    __half2 h = __floats2half2_rn(a, b);
    return *reinterpret_cast<uint32_t*>(&h);
}

__device__ __forceinline__ void mma16816(float* d,
    uint32_t a0, uint32_t a1, uint32_t a2, uint32_t a3,
    uint32_t b0, uint32_t b1)
{
    asm volatile(
        "mma.sync.aligned.m16n8k16.row.col.f32.f16.f16.f32 "
        "{%0,%1,%2,%3}, {%4,%5,%6,%7}, {%8,%9}, {%0,%1,%2,%3};\n"
        : "+f"(d[0]), "+f"(d[1]), "+f"(d[2]), "+f"(d[3])
        : "r"(a0), "r"(a1), "r"(a2), "r"(a3), "r"(b0), "r"(b1));
}

__device__ __forceinline__ void ldsm4(uint32_t& a0, uint32_t& a1,
                                      uint32_t& a2, uint32_t& a3, uint32_t saddr)
{
    asm volatile("ldmatrix.sync.aligned.m8n8.x4.shared.b16 {%0,%1,%2,%3}, [%4];"
                 : "=r"(a0), "=r"(a1), "=r"(a2), "=r"(a3) : "r"(saddr));
}

// hardware tanh (MUFU.TANH): 1 MUFU op
__device__ __forceinline__ float tanhg(float x) {
    float y; asm("tanh.approx.f32 %0, %1;" : "=f"(y) : "f"(x)); return y;
}
// sigmoid via tanh identity: 1 MUFU + 1 FMA
__device__ __forceinline__ float sigg(float x) {
    return __fmaf_rn(0.5f, tanhg(0.5f * x), 0.5f);
}

// ---------------------------------------------------------------------------
// Phase 1: Xg = x@W_ih^T + (b_ih+b_hh), packed fp16 [m][hcol][gate].
// (unchanged from R5 — 154us)
// ---------------------------------------------------------------------------
__global__ void __launch_bounds__(512, 1)
pregemm_kernel(const float* __restrict__ x,
               const float* __restrict__ Wih,
               const float* __restrict__ bih,
               const float* __restrict__ bhh)
{
    __shared__ __half Ash[2][32][136];

    const int tid  = threadIdx.x;
    const int warp = tid >> 5;
    const int lane = tid & 31;
    const int q    = lane & 3;
    const int r0   = lane >> 2;
    const int c0   = warp * 8 + q * 2;

    uint32_t bfrag[4][8][2];
#pragma unroll
    for (int j = 0; j < 4; j++) {
        const float* wr = Wih + (size_t)(j * 128 + warp * 8 + r0) * IDIM;
#pragma unroll
        for (int kt = 0; kt < 8; kt++) {
            const int k = kt * 16 + q * 2;
            float2 w0 = *reinterpret_cast<const float2*>(wr + k);
            float2 w1 = *reinterpret_cast<const float2*>(wr + k + 8);
            bfrag[j][kt][0] = f2h2(w0.x, w0.y);
            bfrag[j][kt][1] = f2h2(w1.x, w1.y);
        }
    }

    float bx[4], by[4];
#pragma unroll
    for (int j = 0; j < 4; j++) {
        bx[j] = bih[j * 128 + c0]     + bhh[j * 128 + c0];
        by[j] = bih[j * 128 + c0 + 1] + bhh[j * 128 + c0 + 1];
    }

    const int lr = tid >> 4;
    const int lc = (tid & 15) * 8;
    const size_t m_base = (size_t)blockIdx.x * 256;

    const int lm_row = lane & 15;
    const int lm_col = (lane >> 4) * 8;

    float4 v0 = *reinterpret_cast<const float4*>(x + (m_base + lr) * IDIM + lc);
    float4 v1 = *reinterpret_cast<const float4*>(x + (m_base + lr) * IDIM + lc + 4);

#pragma unroll 1
    for (int s = 0; s < 8; s++) {
        const int buf = s & 1;
        {
            __half2* sp = reinterpret_cast<__half2*>(&Ash[buf][lr][lc]);
            sp[0] = __floats2half2_rn(v0.x, v0.y);
            sp[1] = __floats2half2_rn(v0.z, v0.w);
            sp[2] = __floats2half2_rn(v1.x, v1.y);
            sp[3] = __floats2half2_rn(v1.z, v1.w);
        }
        __syncthreads();

        if (s < 7) {
            const size_t mr = m_base + (s + 1) * 32 + lr;
            v0 = *reinterpret_cast<const float4*>(x + mr * IDIM + lc);
            v1 = *reinterpret_cast<const float4*>(x + mr * IDIM + lc + 4);
        }

        float acc[2][4][4];
#pragma unroll
        for (int mi = 0; mi < 2; mi++)
#pragma unroll
            for (int j = 0; j < 4; j++)
#pragma unroll
                for (int p = 0; p < 4; p++) acc[mi][j][p] = 0.0f;

#pragma unroll
        for (int kt = 0; kt < 8; kt++) {
#pragma unroll
            for (int mi = 0; mi < 2; mi++) {
                uint32_t a0, a1, a2, a3;
                uint32_t saddr = (uint32_t)__cvta_generic_to_shared(
                    &Ash[buf][mi * 16 + lm_row][kt * 16 + lm_col]);
                ldsm4(a0, a1, a2, a3, saddr);
#pragma unroll
                for (int j = 0; j < 4; j++)
                    mma16816(acc[mi][j], a0, a1, a2, a3, bfrag[j][kt][0], bfrag[j][kt][1]);
            }
        }

        const size_t m0 = m_base + s * 32;
#pragma unroll
        for (int mi = 0; mi < 2; mi++) {
#pragma unroll
            for (int half_ = 0; half_ < 2; half_++) {
                const size_t row = m0 + mi * 16 + r0 + half_ * 8;
                const int pa = half_ * 2;
                uint4 v;
                v.x = f2h2(acc[mi][0][pa]     + bx[0], acc[mi][1][pa]     + bx[1]);
                v.y = f2h2(acc[mi][2][pa]     + bx[2], acc[mi][3][pa]     + bx[3]);
                v.z = f2h2(acc[mi][0][pa + 1] + by[0], acc[mi][1][pa + 1] + by[1]);
                v.w = f2h2(acc[mi][2][pa + 1] + by[2], acc[mi][3][pa + 1] + by[3]);
                *reinterpret_cast<uint4*>(&g_XgH[(row * 128 + c0) * 4]) = v;
            }
        }
    }
}

// ---------------------------------------------------------------------------
// Phase 2: masked LSTM recurrence — transposed W-stationary GEMM,
// pre-fragmented B (R8), gate-interleaved tiles (R9), and FULLY IN-REGISTER
// gate epilogue: B columns 4-7 are read-addressed duplicates of 0-3 (lanes
// 16-31 read slot lane&15), so lane (r0,q) holds all four gates of element
// (col = 8w+r0, n = 2*(q&1) + (q>>1)) in its accumulators -> gate exchange
// is 4 register selects. No STS/LDS/syncwarp for gates at all.
// One __syncthreads per step (h publish). 16 MMA/warp/step.
// Grid 128 blocks x 4 batch rows, 512 threads.
// ---------------------------------------------------------------------------
__global__ void __launch_bounds__(512, 1)
lstm_rec_kernel(const float* __restrict__ hc,
                const int*   __restrict__ is_init,
                const float* __restrict__ Whh,
                float* __restrict__ out)
{
    __shared__ uint2 bbuf[2][8][16];      // pre-fragmented h (2KB)
    __shared__ float msk[LSEQ][4];        // mask table (8KB)

    const int tid  = threadIdx.x;
    const int warp = tid >> 5;
    const int lane = tid & 31;
    const int q    = lane & 3;
    const int r0   = lane >> 2;
    const int n0   = blockIdx.x * 4;

    // in-register element ownership: lane (r0,q) -> (col, nsel)
    const int col  = warp * 8 + r0;             // global hcol
    const int nsel = 2 * (q & 1) + (q >> 1);    // batch row 0..3
    const int hi   = q >> 1;                    // accumulator parity
    const int n    = n0 + nsel;

    // fragment-slot address for this lane's h element (bbuf layout):
    // bbuf[buf][kt][l16].{x,y} ; kt = col>>4, fr = col&15, slot n = l16>>2
    const int fkt  = col >> 4;
    const int fr   = col & 15;
    const int fl16 = nsel * 4 + ((fr & 7) >> 1);
    const uint32_t fragOff = (uint32_t)(((fkt * 16 + fl16) * 8) +
                                        ((fr & 8) ? 4 : 0) + (col & 1) * 2);
    const uint32_t bbufBase0 = (uint32_t)__cvta_generic_to_shared(&bbuf[0][0][0]);
    const uint32_t bbufBase1 = (uint32_t)__cvta_generic_to_shared(&bbuf[1][0][0]);

    // --- A-fragments (gate-interleaved tiles), loaded once ---
    // tile mt: rows 0-7 = gate 2mt, rows 8-15 = gate 2mt+1, hcols [8w,8w+8)
    uint32_t afrag[2][8][4];
#pragma unroll
    for (int mt = 0; mt < 2; mt++) {
        const float* wlo = Whh + (size_t)((2 * mt)     * 128 + warp * 8 + r0) * HDIM;
        const float* whi = Whh + (size_t)((2 * mt + 1) * 128 + warp * 8 + r0) * HDIM;
#pragma unroll
        for (int kt = 0; kt < 8; kt++) {
            const int k = kt * 16 + q * 2;
            float2 w00 = *reinterpret_cast<const float2*>(wlo + k);
            float2 w01 = *reinterpret_cast<const float2*>(wlo + k + 8);
            float2 w10 = *reinterpret_cast<const float2*>(whi + k);
            float2 w11 = *reinterpret_cast<const float2*>(whi + k + 8);
            afrag[mt][kt][0] = f2h2(w00.x, w00.y);   // row r0     (gate 2mt)
            afrag[mt][kt][1] = f2h2(w10.x, w10.y);   // row r0+8   (gate 2mt+1)
            afrag[mt][kt][2] = f2h2(w01.x, w01.y);
            afrag[mt][kt][3] = f2h2(w11.x, w11.y);
        }
    }

    // --- mask table ---
    for (int idx = tid; idx < LSEQ * 4; idx += 512) {
        const int t = idx >> 2, r = idx & 3;
        msk[t][r] = 1.0f - (float)is_init[(size_t)t * NBATCH + n0 + r];
    }
    __syncthreads();

    // --- init state (t=0 mask applied); write h0 into fragment slot ---
    const float m0v = msk[0][nsel];
    float creg = hc[(size_t)n * 256 + 128 + col] * m0v;
    {
        const __half h0 = __float2half(hc[(size_t)n * 256 + col] * m0v);
        const uint16_t hb = *reinterpret_cast<const uint16_t*>(&h0);
        asm volatile("st.shared.u16 [%0], %1;" :: "r"(bbufBase0 + fragOff), "h"(hb));
    }
    __syncthreads();

    // per-lane Xg pointer: 8B per (m, hcol)
    const uint2* xgp = reinterpret_cast<const uint2*>(g_XgH);
    uint2 xcur = __ldg(&xgp[(size_t)n * 128 + col]);     // t = 0

    // B-fragment read address: one LDS.64 per kt, lane&15 slot (16-31 broadcast)
    const uint32_t bRead0 = bbufBase0 + (uint32_t)(lane & 15) * 8;
    const uint32_t bRead1 = bbufBase1 + (uint32_t)(lane & 15) * 8;

    const size_t OUT_HC = (size_t)LSEQ * NBATCH * HDIM;

#pragma unroll 1
    for (int t = 0; t < LSEQ; t++) {
        // prefetch next step's Xg (array padded by 1 step)
        uint2 xnext = __ldg(&xgp[((size_t)(t + 1) * NBATCH + n) * 128 + col]);

        // --- MMA: 2 gate-interleaved m16 tiles x 8 kt, split acc chains ---
        float acc[2][4], accB[2][4];
#pragma unroll
        for (int mt = 0; mt < 2; mt++)
#pragma unroll
            for (int p = 0; p < 4; p++) { acc[mt][p] = 0.0f; accB[mt][p] = 0.0f; }

        const uint32_t brd = (t & 1) ? bRead1 : bRead0;
#pragma unroll
        for (int kt = 0; kt < 4; kt++) {
            uint32_t b0, b1, c0_, c1_;
            asm volatile("ld.shared.v2.u32 {%0,%1}, [%2];"
                         : "=r"(b0), "=r"(b1) : "r"(brd + kt * 128));
            asm volatile("ld.shared.v2.u32 {%0,%1}, [%2];"
                         : "=r"(c0_), "=r"(c1_) : "r"(brd + (kt + 4) * 128));
#pragma unroll
            for (int mt = 0; mt < 2; mt++) {
                mma16816(acc[mt],  afrag[mt][kt][0],     afrag[mt][kt][1],
                                   afrag[mt][kt][2],     afrag[mt][kt][3],     b0, b1);
                mma16816(accB[mt], afrag[mt][kt + 4][0], afrag[mt][kt + 4][1],
                                   afrag[mt][kt + 4][2], afrag[mt][kt + 4][3], c0_, c1_);
            }
        }

        // gate values for this lane's element: all in-register (parity select)
        // acc[0] = {i(nA), i(nB), f(nA), f(nB)}, acc[1] = {g.., o..};
        // lane's batch column = 2*(q&1) + parity hi within its pair
        const float gi = (hi ? acc[0][1] + accB[0][1] : acc[0][0] + accB[0][0]);
        const float gf = (hi ? acc[0][3] + accB[0][3] : acc[0][2] + accB[0][2]);
        const float gg = (hi ? acc[1][1] + accB[1][1] : acc[1][0] + accB[1][0]);
        const float go = (hi ? acc[1][3] + accB[1][3] : acc[1][2] + accB[1][2]);

        // --- epilogue: 1 element per lane (gate order i,f,g,o) ---
        const float2 x01 = __half22float2(*reinterpret_cast<__half2*>(&xcur.x));
        const float2 x23 = __half22float2(*reinterpret_cast<__half2*>(&xcur.y));

        const float i_ = sigg(gi + x01.x);
        const float f_ = sigg(gf + x01.y);
        const float g_ = tanhg(gg + x23.x);
        const float o_ = sigg(go + x23.y);
        const float cn = __fmaf_rn(f_, creg, i_ * g_);
        const float hv = o_ * tanhg(cn);

        out[((size_t)t * NBATCH + n) * HDIM + col] = hv;

        const float mn = (t < LSEQ - 1) ? msk[t + 1][nsel] : 1.0f;
        creg = cn * mn;

        // write next-step h directly into its fragment slot
        {
            const __half hm = __float2half(hv * mn);
            const uint16_t hb = *reinterpret_cast<const uint16_t*>(&hm);
            const uint32_t dst = ((t + 1) & 1) ? bbufBase1 : bbufBase0;
            asm volatile("st.shared.u16 [%0], %1;" :: "r"(dst + fragOff), "h"(hb));
        }

        if (t == LSEQ - 1) {
            out[OUT_HC + (size_t)n * 256 + col]       = hv;
            out[OUT_HC + (size_t)n * 256 + 128 + col] = cn;
        }
        __syncthreads();   // h(t+1) visible to all warps (only barrier per step)
        xcur = xnext;
    }
}

// ---------------------------------------------------------------------------
extern "C" void kernel_launch(void* const* d_in, const int* in_sizes, int n_in,
                              void* d_out, int out_size)
{
    const float* input   = (const float*)d_in[0];  // [L,N,I] fp32
    const float* hc      = (const float*)d_in[1];  // [N,2H]  fp32
    const int*   is_init = (const int*)  d_in[2];  // [L,N]   int32
    const float* Wih     = (const float*)d_in[3];  // [4H,I]
    const float* Whh     = (const float*)d_in[4];  // [4H,H]
    const float* bih     = (const float*)d_in[5];  // [4H]
    const float* bhh     = (const float*)d_in[6];  // [4H]
    float* out = (float*)d_out;                    // [L,N,H] then [N,2H]

    pregemm_kernel<<<(LSEQ * NBATCH) / 256, 512>>>(input, Wih, bih, bhh);
    lstm_rec_kernel<<<NBATCH / 4, 512>>>(hc, is_init, Whh, out);
}

// round 11
// speedup vs baseline: 1.2277x; 1.0048x over previous
#include <cuda_runtime.h>
#include <cuda_fp16.h>
#include <cstdint>
#include <cstddef>

#define LSEQ 512
#define NBATCH 512
#define IDIM 128
#define HDIM 128
#define GDIM 512   // 4*H

// Scratch: packed fp16 pre-activation input gates.
// Layout: [m = t*N+n][hcol 0..127][gate 0..3]  -> 8 bytes per (m, hcol)
// Padded by 1 step so the t+1 prefetch needs no bounds check.
__device__ __half g_XgH[(size_t)(LSEQ + 1) * NBATCH * GDIM];

// ---------------------------------------------------------------------------
// helpers
// ---------------------------------------------------------------------------
__device__ __forceinline__ uint32_t f2h2(float a, float b) {
    __half2 h = __floats2half2_rn(a, b);
    return *reinterpret_cast<uint32_t*>(&h);
}

__device__ __forceinline__ void mma16816(float* d,
    uint32_t a0, uint32_t a1, uint32_t a2, uint32_t a3,
    uint32_t b0, uint32_t b1)
{
    asm volatile(
        "mma.sync.aligned.m16n8k16.row.col.f32.f16.f16.f32 "
        "{%0,%1,%2,%3}, {%4,%5,%6,%7}, {%8,%9}, {%0,%1,%2,%3};\n"
        : "+f"(d[0]), "+f"(d[1]), "+f"(d[2]), "+f"(d[3])
        : "r"(a0), "r"(a1), "r"(a2), "r"(a3), "r"(b0), "r"(b1));
}

__device__ __forceinline__ void ldsm4(uint32_t& a0, uint32_t& a1,
                                      uint32_t& a2, uint32_t& a3, uint32_t saddr)
{
    asm volatile("ldmatrix.sync.aligned.m8n8.x4.shared.b16 {%0,%1,%2,%3}, [%4];"
                 : "=r"(a0), "=r"(a1), "=r"(a2), "=r"(a3) : "r"(saddr));
}

// hardware tanh (MUFU.TANH): 1 MUFU op
__device__ __forceinline__ float tanhg(float x) {
    float y; asm("tanh.approx.f32 %0, %1;" : "=f"(y) : "f"(x)); return y;
}
// sigmoid via tanh identity: 1 MUFU + 1 FMA
__device__ __forceinline__ float sigg(float x) {
    return __fmaf_rn(0.5f, tanhg(0.5f * x), 0.5f);
}

// named barrier arrive/sync (count covers 512 arrives + 512 syncs per phase)
__device__ __forceinline__ void nbar_arrive(int id) {
    asm volatile("bar.arrive %0, 1024;" :: "r"(id) : "memory");
}
__device__ __forceinline__ void nbar_sync(int id) {
    asm volatile("bar.sync %0, 1024;" :: "r"(id) : "memory");
}

// ---------------------------------------------------------------------------
// Phase 1: Xg = x@W_ih^T + (b_ih+b_hh), packed fp16 [m][hcol][gate].
// Grid 512 x 512 threads, 512 M-rows/block (16 subtiles) — halves the
// per-row amortized W_ih fragment-load prologue vs 256 rows/block.
// ---------------------------------------------------------------------------
__global__ void __launch_bounds__(512, 1)
pregemm_kernel(const float* __restrict__ x,
               const float* __restrict__ Wih,
               const float* __restrict__ bih,
               const float* __restrict__ bhh)
{
    __shared__ __half Ash[2][32][136];

    const int tid  = threadIdx.x;
    const int warp = tid >> 5;
    const int lane = tid & 31;
    const int q    = lane & 3;
    const int r0   = lane >> 2;
    const int c0   = warp * 8 + q * 2;

    uint32_t bfrag[4][8][2];
#pragma unroll
    for (int j = 0; j < 4; j++) {
        const float* wr = Wih + (size_t)(j * 128 + warp * 8 + r0) * IDIM;
#pragma unroll
        for (int kt = 0; kt < 8; kt++) {
            const int k = kt * 16 + q * 2;
            float2 w0 = *reinterpret_cast<const float2*>(wr + k);
            float2 w1 = *reinterpret_cast<const float2*>(wr + k + 8);
            bfrag[j][kt][0] = f2h2(w0.x, w0.y);
            bfrag[j][kt][1] = f2h2(w1.x, w1.y);
        }
    }

    float bx[4], by[4];
#pragma unroll
    for (int j = 0; j < 4; j++) {
        bx[j] = bih[j * 128 + c0]     + bhh[j * 128 + c0];
        by[j] = bih[j * 128 + c0 + 1] + bhh[j * 128 + c0 + 1];
    }

    const int lr = tid >> 4;
    const int lc = (tid & 15) * 8;
    const size_t m_base = (size_t)blockIdx.x * 512;

    const int lm_row = lane & 15;
    const int lm_col = (lane >> 4) * 8;

    float4 v0 = *reinterpret_cast<const float4*>(x + (m_base + lr) * IDIM + lc);
    float4 v1 = *reinterpret_cast<const float4*>(x + (m_base + lr) * IDIM + lc + 4);

#pragma unroll 1
    for (int s = 0; s < 16; s++) {
        const int buf = s & 1;
        {
            __half2* sp = reinterpret_cast<__half2*>(&Ash[buf][lr][lc]);
            sp[0] = __floats2half2_rn(v0.x, v0.y);
            sp[1] = __floats2half2_rn(v0.z, v0.w);
            sp[2] = __floats2half2_rn(v1.x, v1.y);
            sp[3] = __floats2half2_rn(v1.z, v1.w);
        }
        __syncthreads();

        if (s < 15) {
            const size_t mr = m_base + (s + 1) * 32 + lr;
            v0 = *reinterpret_cast<const float4*>(x + mr * IDIM + lc);
            v1 = *reinterpret_cast<const float4*>(x + mr * IDIM + lc + 4);
        }

        float acc[2][4][4];
#pragma unroll
        for (int mi = 0; mi < 2; mi++)
#pragma unroll
            for (int j = 0; j < 4; j++)
#pragma unroll
                for (int p = 0; p < 4; p++) acc[mi][j][p] = 0.0f;

#pragma unroll
        for (int kt = 0; kt < 8; kt++) {
#pragma unroll
            for (int mi = 0; mi < 2; mi++) {
                uint32_t a0, a1, a2, a3;
                uint32_t saddr = (uint32_t)__cvta_generic_to_shared(
                    &Ash[buf][mi * 16 + lm_row][kt * 16 + lm_col]);
                ldsm4(a0, a1, a2, a3, saddr);
#pragma unroll
                for (int j = 0; j < 4; j++)
                    mma16816(acc[mi][j], a0, a1, a2, a3, bfrag[j][kt][0], bfrag[j][kt][1]);
            }
        }

        const size_t m0 = m_base + s * 32;
#pragma unroll
        for (int mi = 0; mi < 2; mi++) {
#pragma unroll
            for (int half_ = 0; half_ < 2; half_++) {
                const size_t row = m0 + mi * 16 + r0 + half_ * 8;
                const int pa = half_ * 2;
                uint4 v;
                v.x = f2h2(acc[mi][0][pa]     + bx[0], acc[mi][1][pa]     + bx[1]);
                v.y = f2h2(acc[mi][2][pa]     + bx[2], acc[mi][3][pa]     + bx[3]);
                v.z = f2h2(acc[mi][0][pa + 1] + by[0], acc[mi][1][pa + 1] + by[1]);
                v.w = f2h2(acc[mi][2][pa + 1] + by[2], acc[mi][3][pa + 1] + by[3]);
                *reinterpret_cast<uint4*>(&g_XgH[(row * 128 + c0) * 4]) = v;
            }
        }
        __syncthreads();
    }
}

// ---------------------------------------------------------------------------
// Phase 2: masked LSTM recurrence — R10 core (transposed W-stationary GEMM,
// pre-fragmented B, gate-interleaved tiles, in-register gate epilogue) with:
//  (a) named-barrier arrive/sync split (ids 1/2 ping-pong, count=1024):
//      publish h -> arrive -> out STG + Xg prefetch + mask read -> next step
//      syncs. Fast warps overlap their tail with slow warps' MMA phase.
//  (b) B-fragments via 4 LDS.128 (kt even/odd packed per 16B slot).
// Grid 128 blocks x 4 batch rows, 512 threads, 16 MMA/warp/step.
// ---------------------------------------------------------------------------
__global__ void __launch_bounds__(512, 1)
lstm_rec_kernel(const float* __restrict__ hc,
                const int*   __restrict__ is_init,
                const float* __restrict__ Whh,
                float* __restrict__ out)
{
    __shared__ uint4 bbuf[2][4][16];      // pre-fragmented h, kt-pairs packed (2KB)
    __shared__ float msk[LSEQ][4];        // mask table (8KB)

    const int tid  = threadIdx.x;
    const int warp = tid >> 5;
    const int lane = tid & 31;
    const int q    = lane & 3;
    const int r0   = lane >> 2;
    const int n0   = blockIdx.x * 4;

    // in-register element ownership: lane (r0,q) -> (col, nsel)
    const int col  = warp * 8 + r0;             // global hcol
    const int nsel = 2 * (q & 1) + (q >> 1);    // batch row 0..3
    const int hi   = q >> 1;                    // accumulator parity
    const int n    = n0 + nsel;

    // fragment-slot byte offset (within one buf) for this lane's h element:
    // bbuf[buf][kt2][l16] 16B slot: +0..7 = kt even (b0@+0/b1@+4), +8..15 = kt odd
    const int fkt  = col >> 4;
    const int fr   = col & 15;
    const int fl16 = nsel * 4 + ((fr & 7) >> 1);
    const uint32_t fragOff = (uint32_t)((((fkt >> 1) * 16 + fl16) * 16) +
                                        (fkt & 1) * 8 +
                                        ((fr & 8) ? 4 : 0) + (col & 1) * 2);
    const uint32_t bbufBase0 = (uint32_t)__cvta_generic_to_shared(&bbuf[0][0][0]);
    const uint32_t bbufBase1 = (uint32_t)__cvta_generic_to_shared(&bbuf[1][0][0]);

    // --- A-fragments (gate-interleaved tiles), loaded once ---
    uint32_t afrag[2][8][4];
#pragma unroll
    for (int mt = 0; mt < 2; mt++) {
        const float* wlo = Whh + (size_t)((2 * mt)     * 128 + warp * 8 + r0) * HDIM;
        const float* whi = Whh + (size_t)((2 * mt + 1) * 128 + warp * 8 + r0) * HDIM;
#pragma unroll
        for (int kt = 0; kt < 8; kt++) {
            const int k = kt * 16 + q * 2;
            float2 w00 = *reinterpret_cast<const float2*>(wlo + k);
            float2 w01 = *reinterpret_cast<const float2*>(wlo + k + 8);
            float2 w10 = *reinterpret_cast<const float2*>(whi + k);
            float2 w11 = *reinterpret_cast<const float2*>(whi + k + 8);
            afrag[mt][kt][0] = f2h2(w00.x, w00.y);   // row r0     (gate 2mt)
            afrag[mt][kt][1] = f2h2(w10.x, w10.y);   // row r0+8   (gate 2mt+1)
            afrag[mt][kt][2] = f2h2(w01.x, w01.y);
            afrag[mt][kt][3] = f2h2(w11.x, w11.y);
        }
    }

    // --- mask table ---
    for (int idx = tid; idx < LSEQ * 4; idx += 512) {
        const int t = idx >> 2, r = idx & 3;
        msk[t][r] = 1.0f - (float)is_init[(size_t)t * NBATCH + n0 + r];
    }
    __syncthreads();

    // --- init state (t=0 mask applied); write h0 into fragment slot ---
    const float m0v = msk[0][nsel];
    float creg = hc[(size_t)n * 256 + 128 + col] * m0v;
    {
        const __half h0 = __float2half(hc[(size_t)n * 256 + col] * m0v);
        const uint16_t hb = *reinterpret_cast<const uint16_t*>(&h0);
        asm volatile("st.shared.u16 [%0], %1;" :: "r"(bbufBase0 + fragOff), "h"(hb));
    }
    __syncthreads();   // h(0) visible; step 0 needs no named-barrier sync

    // per-lane Xg pointer: 8B per (m, hcol)
    const uint2* xgp = reinterpret_cast<const uint2*>(g_XgH);
    uint2 xcur = __ldg(&xgp[(size_t)n * 128 + col]);     // t = 0

    // B-fragment read base: 4 x LDS.128 at slot lane&15 (lanes 16-31 broadcast)
    const uint32_t bRead0 = bbufBase0 + (uint32_t)(lane & 15) * 16;
    const uint32_t bRead1 = bbufBase1 + (uint32_t)(lane & 15) * 16;

    const size_t OUT_HC = (size_t)LSEQ * NBATCH * HDIM;
    float* outp = out + (size_t)n * HDIM + col;          // advances 64K floats/step

#pragma unroll 1
    for (int t = 0; t < LSEQ; t++) {
        // issue long-latency, state-independent work BEFORE the sync
        uint2 xnext = __ldg(&xgp[((size_t)(t + 1) * NBATCH + n) * 128 + col]);
        const float mn = (t < LSEQ - 1) ? msk[t + 1][nsel] : 1.0f;

        if (t) nbar_sync(1 + (t & 1));    // wait for h(t) publication

        // --- MMA: 2 gate-interleaved m16 tiles x 8 kt, split acc chains ---
        float acc[2][4], accB[2][4];
#pragma unroll
        for (int mt = 0; mt < 2; mt++)
#pragma unroll
            for (int p = 0; p < 4; p++) { acc[mt][p] = 0.0f; accB[mt][p] = 0.0f; }

        const uint32_t brd = (t & 1) ? bRead1 : bRead0;
#pragma unroll
        for (int kt2 = 0; kt2 < 4; kt2++) {
            uint32_t b0, b1, c0_, c1_;    // kt=2*kt2 pair, kt=2*kt2+1 pair
            asm volatile("ld.shared.v4.u32 {%0,%1,%2,%3}, [%4];"
                         : "=r"(b0), "=r"(b1), "=r"(c0_), "=r"(c1_)
                         : "r"(brd + kt2 * 256));
#pragma unroll
            for (int mt = 0; mt < 2; mt++) {
                mma16816(acc[mt],  afrag[mt][2*kt2][0],   afrag[mt][2*kt2][1],
                                   afrag[mt][2*kt2][2],   afrag[mt][2*kt2][3],   b0, b1);
                mma16816(accB[mt], afrag[mt][2*kt2+1][0], afrag[mt][2*kt2+1][1],
                                   afrag[mt][2*kt2+1][2], afrag[mt][2*kt2+1][3], c0_, c1_);
            }
        }

        // gate values for this lane's element: all in-register (parity select)
        const float gi = (hi ? acc[0][1] + accB[0][1] : acc[0][0] + accB[0][0]);
        const float gf = (hi ? acc[0][3] + accB[0][3] : acc[0][2] + accB[0][2]);
        const float gg = (hi ? acc[1][1] + accB[1][1] : acc[1][0] + accB[1][0]);
        const float go = (hi ? acc[1][3] + accB[1][3] : acc[1][2] + accB[1][2]);

        // --- epilogue: 1 element per lane (gate order i,f,g,o) ---
        const float2 x01 = __half22float2(*reinterpret_cast<__half2*>(&xcur.x));
        const float2 x23 = __half22float2(*reinterpret_cast<__half2*>(&xcur.y));

        const float i_ = sigg(gi + x01.x);
        const float f_ = sigg(gf + x01.y);
        const float g_ = tanhg(gg + x23.x);
        const float o_ = sigg(go + x23.y);
        const float cn = __fmaf_rn(f_, creg, i_ * g_);
        const float hv = o_ * tanhg(cn);

        creg = cn * mn;

        // publish next-step h into its fragment slot, then arrive
        {
            const __half hm = __float2half(hv * mn);
            const uint16_t hb = *reinterpret_cast<const uint16_t*>(&hm);
            const uint32_t dst = ((t + 1) & 1) ? bbufBase1 : bbufBase0;
            asm volatile("st.shared.u16 [%0], %1;" :: "r"(dst + fragOff), "h"(hb));
        }
        nbar_arrive(1 + ((t + 1) & 1));

        // long-latency tail AFTER arrive (overlaps other warps' next MMA)
        *outp = hv;
        outp += (size_t)NBATCH * HDIM;

        if (t == LSEQ - 1) {
            out[OUT_HC + (size_t)n * 256 + col]       = hv;
            out[OUT_HC + (size_t)n * 256 + 128 + col] = cn;
        }
        xcur = xnext;
    }
}

// ---------------------------------------------------------------------------
extern "C" void kernel_launch(void* const* d_in, const int* in_sizes, int n_in,
                              void* d_out, int out_size)
{
    const float* input   = (const float*)d_in[0];  // [L,N,I] fp32
    const float* hc      = (const float*)d_in[1];  // [N,2H]  fp32
    const int*   is_init = (const int*)  d_in[2];  // [L,N]   int32
    const float* Wih     = (const float*)d_in[3];  // [4H,I]
    const float* Whh     = (const float*)d_in[4];  // [4H,H]
    const float* bih     = (const float*)d_in[5];  // [4H]
    const float* bhh     = (const float*)d_in[6];  // [4H]
    float* out = (float*)d_out;                    // [L,N,H] then [N,2H]

    pregemm_kernel<<<(LSEQ * NBATCH) / 512, 512>>>(input, Wih, bih, bhh);
    lstm_rec_kernel<<<NBATCH / 4, 512>>>(hc, is_init, Whh, out);
}

// round 12
// speedup vs baseline: 1.2425x; 1.0121x over previous
#include <cuda_runtime.h>
#include <cuda_fp16.h>
#include <cstdint>
#include <cstddef>

#define LSEQ 512
#define NBATCH 512
#define IDIM 128
#define HDIM 128
#define GDIM 512   // 4*H

// Scratch: packed fp16 pre-activation input gates.
// Layout: [m = t*N+n][hcol 0..127][gate 0..3]  -> 8 bytes per (m, hcol)
// Padded by 1 step so the t+1 prefetch needs no bounds check.
__device__ __half g_XgH[(size_t)(LSEQ + 1) * NBATCH * GDIM];

// ---------------------------------------------------------------------------
// helpers
// ---------------------------------------------------------------------------
__device__ __forceinline__ uint32_t f2h2(float a, float b) {
    __half2 h = __floats2half2_rn(a, b);
    return *reinterpret_cast<uint32_t*>(&h);
}

__device__ __forceinline__ void mma16816(float* d,
    uint32_t a0, uint32_t a1, uint32_t a2, uint32_t a3,
    uint32_t b0, uint32_t b1)
{
    asm volatile(
        "mma.sync.aligned.m16n8k16.row.col.f32.f16.f16.f32 "
        "{%0,%1,%2,%3}, {%4,%5,%6,%7}, {%8,%9}, {%0,%1,%2,%3};\n"
        : "+f"(d[0]), "+f"(d[1]), "+f"(d[2]), "+f"(d[3])
        : "r"(a0), "r"(a1), "r"(a2), "r"(a3), "r"(b0), "r"(b1));
}

__device__ __forceinline__ void ldsm4(uint32_t& a0, uint32_t& a1,
                                      uint32_t& a2, uint32_t& a3, uint32_t saddr)
{
    asm volatile("ldmatrix.sync.aligned.m8n8.x4.shared.b16 {%0,%1,%2,%3}, [%4];"
                 : "=r"(a0), "=r"(a1), "=r"(a2), "=r"(a3) : "r"(saddr));
}

// hardware tanh (MUFU.TANH): 1 MUFU op
__device__ __forceinline__ float tanhg(float x) {
    float y; asm("tanh.approx.f32 %0, %1;" : "=f"(y) : "f"(x)); return y;
}
// sigmoid via tanh identity: 1 MUFU + 1 FMA
__device__ __forceinline__ float sigg(float x) {
    return __fmaf_rn(0.5f, tanhg(0.5f * x), 0.5f);
}

// half-K handoff barriers: 256 arrivers (8 warps) + 512 syncers = 768
__device__ __forceinline__ void nbar_sync768(int id) {
    asm volatile("bar.sync %0, 768;" :: "r"(id) : "memory");
}
__device__ __forceinline__ void nbar_arrive768(int id) {
    asm volatile("bar.arrive %0, 768;" :: "r"(id) : "memory");
}

// ---------------------------------------------------------------------------
// Phase 1: Xg = x@W_ih^T + (b_ih+b_hh), packed fp16 [m][hcol][gate].
// Grid 512 x 512 threads, 512 M-rows/block (16 subtiles).
// ---------------------------------------------------------------------------
__global__ void __launch_bounds__(512, 1)
pregemm_kernel(const float* __restrict__ x,
               const float* __restrict__ Wih,
               const float* __restrict__ bih,
               const float* __restrict__ bhh)
{
    __shared__ __half Ash[2][32][136];

    const int tid  = threadIdx.x;
    const int warp = tid >> 5;
    const int lane = tid & 31;
    const int q    = lane & 3;
    const int r0   = lane >> 2;
    const int c0   = warp * 8 + q * 2;

    uint32_t bfrag[4][8][2];
#pragma unroll
    for (int j = 0; j < 4; j++) {
        const float* wr = Wih + (size_t)(j * 128 + warp * 8 + r0) * IDIM;
#pragma unroll
        for (int kt = 0; kt < 8; kt++) {
            const int k = kt * 16 + q * 2;
            float2 w0 = *reinterpret_cast<const float2*>(wr + k);
            float2 w1 = *reinterpret_cast<const float2*>(wr + k + 8);
            bfrag[j][kt][0] = f2h2(w0.x, w0.y);
            bfrag[j][kt][1] = f2h2(w1.x, w1.y);
        }
    }

    float bx[4], by[4];
#pragma unroll
    for (int j = 0; j < 4; j++) {
        bx[j] = bih[j * 128 + c0]     + bhh[j * 128 + c0];
        by[j] = bih[j * 128 + c0 + 1] + bhh[j * 128 + c0 + 1];
    }

    const int lr = tid >> 4;
    const int lc = (tid & 15) * 8;
    const size_t m_base = (size_t)blockIdx.x * 512;

    const int lm_row = lane & 15;
    const int lm_col = (lane >> 4) * 8;

    float4 v0 = *reinterpret_cast<const float4*>(x + (m_base + lr) * IDIM + lc);
    float4 v1 = *reinterpret_cast<const float4*>(x + (m_base + lr) * IDIM + lc + 4);

#pragma unroll 1
    for (int s = 0; s < 16; s++) {
        const int buf = s & 1;
        {
            __half2* sp = reinterpret_cast<__half2*>(&Ash[buf][lr][lc]);
            sp[0] = __floats2half2_rn(v0.x, v0.y);
            sp[1] = __floats2half2_rn(v0.z, v0.w);
            sp[2] = __floats2half2_rn(v1.x, v1.y);
            sp[3] = __floats2half2_rn(v1.z, v1.w);
        }
        __syncthreads();

        if (s < 15) {
            const size_t mr = m_base + (s + 1) * 32 + lr;
            v0 = *reinterpret_cast<const float4*>(x + mr * IDIM + lc);
            v1 = *reinterpret_cast<const float4*>(x + mr * IDIM + lc + 4);
        }

        float acc[2][4][4];
#pragma unroll
        for (int mi = 0; mi < 2; mi++)
#pragma unroll
            for (int j = 0; j < 4; j++)
#pragma unroll
                for (int p = 0; p < 4; p++) acc[mi][j][p] = 0.0f;

#pragma unroll
        for (int kt = 0; kt < 8; kt++) {
#pragma unroll
            for (int mi = 0; mi < 2; mi++) {
                uint32_t a0, a1, a2, a3;
                uint32_t saddr = (uint32_t)__cvta_generic_to_shared(
                    &Ash[buf][mi * 16 + lm_row][kt * 16 + lm_col]);
                ldsm4(a0, a1, a2, a3, saddr);
#pragma unroll
                for (int j = 0; j < 4; j++)
                    mma16816(acc[mi][j], a0, a1, a2, a3, bfrag[j][kt][0], bfrag[j][kt][1]);
            }
        }

        const size_t m0 = m_base + s * 32;
#pragma unroll
        for (int mi = 0; mi < 2; mi++) {
#pragma unroll
            for (int half_ = 0; half_ < 2; half_++) {
                const size_t row = m0 + mi * 16 + r0 + half_ * 8;
                const int pa = half_ * 2;
                uint4 v;
                v.x = f2h2(acc[mi][0][pa]     + bx[0], acc[mi][1][pa]     + bx[1]);
                v.y = f2h2(acc[mi][2][pa]     + bx[2], acc[mi][3][pa]     + bx[3]);
                v.z = f2h2(acc[mi][0][pa + 1] + by[0], acc[mi][1][pa + 1] + by[1]);
                v.w = f2h2(acc[mi][2][pa + 1] + by[2], acc[mi][3][pa + 1] + by[3]);
                *reinterpret_cast<uint4*>(&g_XgH[(row * 128 + c0) * 4]) = v;
            }
        }
        __syncthreads();
    }
}

// ---------------------------------------------------------------------------
// Phase 2: masked LSTM recurrence — R10/R11 core with HALF-K HANDOFF:
// warp w publishes h cols [8w,8w+8). K-chunk {kt2 0,1} consumes cols 0-63
// (warps 0-7), chunk {kt2 2,3} consumes cols 64-127 (warps 8-15). Two named
// barriers per step (ping-pong ids {1,2}/{3,4}): warps 0-7 arrive A, 8-15
// arrive B after their STS; every warp syncs A before chunk01 and B before
// chunk23. Late warps' epilogue/MUFU/STG overlaps early MMA chunks of the
// whole block instead of convoying behind one block barrier.
// Grid 128 blocks x 4 batch rows, 512 threads, 16 MMA/warp/step.
// ---------------------------------------------------------------------------
__global__ void __launch_bounds__(512, 1)
lstm_rec_kernel(const float* __restrict__ hc,
                const int*   __restrict__ is_init,
                const float* __restrict__ Whh,
                float* __restrict__ out)
{
    __shared__ uint4 bbuf[2][4][16];      // pre-fragmented h, kt-pairs packed (2KB)
    __shared__ float msk[LSEQ][4];        // mask table (8KB)

    const int tid  = threadIdx.x;
    const int warp = tid >> 5;
    const int lane = tid & 31;
    const int q    = lane & 3;
    const int r0   = lane >> 2;
    const int n0   = blockIdx.x * 4;

    // in-register element ownership: lane (r0,q) -> (col, nsel)
    const int col  = warp * 8 + r0;             // global hcol
    const int nsel = 2 * (q & 1) + (q >> 1);    // batch row 0..3
    const int hi   = q >> 1;                    // accumulator parity
    const int n    = n0 + nsel;
    const int myHalf = warp >> 3;               // which handoff barrier I feed

    // fragment-slot byte offset (within one buf) for this lane's h element:
    // bbuf[buf][kt2][l16] 16B slot: +0..7 = kt even (b0@+0/b1@+4), +8..15 = kt odd
    const int fkt  = col >> 4;
    const int fr   = col & 15;
    const int fl16 = nsel * 4 + ((fr & 7) >> 1);
    const uint32_t fragOff = (uint32_t)((((fkt >> 1) * 16 + fl16) * 16) +
                                        (fkt & 1) * 8 +
                                        ((fr & 8) ? 4 : 0) + (col & 1) * 2);
    const uint32_t bbufBase0 = (uint32_t)__cvta_generic_to_shared(&bbuf[0][0][0]);
    const uint32_t bbufBase1 = (uint32_t)__cvta_generic_to_shared(&bbuf[1][0][0]);

    // --- A-fragments (gate-interleaved tiles), loaded once ---
    uint32_t afrag[2][8][4];
#pragma unroll
    for (int mt = 0; mt < 2; mt++) {
        const float* wlo = Whh + (size_t)((2 * mt)     * 128 + warp * 8 + r0) * HDIM;
        const float* whi = Whh + (size_t)((2 * mt + 1) * 128 + warp * 8 + r0) * HDIM;
#pragma unroll
        for (int kt = 0; kt < 8; kt++) {
            const int k = kt * 16 + q * 2;
            float2 w00 = *reinterpret_cast<const float2*>(wlo + k);
            float2 w01 = *reinterpret_cast<const float2*>(wlo + k + 8);
            float2 w10 = *reinterpret_cast<const float2*>(whi + k);
            float2 w11 = *reinterpret_cast<const float2*>(whi + k + 8);
            afrag[mt][kt][0] = f2h2(w00.x, w00.y);   // row r0     (gate 2mt)
            afrag[mt][kt][1] = f2h2(w10.x, w10.y);   // row r0+8   (gate 2mt+1)
            afrag[mt][kt][2] = f2h2(w01.x, w01.y);
            afrag[mt][kt][3] = f2h2(w11.x, w11.y);
        }
    }

    // --- mask table ---
    for (int idx = tid; idx < LSEQ * 4; idx += 512) {
        const int t = idx >> 2, r = idx & 3;
        msk[t][r] = 1.0f - (float)is_init[(size_t)t * NBATCH + n0 + r];
    }
    __syncthreads();

    // --- init state (t=0 mask applied); write h0 into fragment slot ---
    const float m0v = msk[0][nsel];
    float creg = hc[(size_t)n * 256 + 128 + col] * m0v;
    {
        const __half h0 = __float2half(hc[(size_t)n * 256 + col] * m0v);
        const uint16_t hb = *reinterpret_cast<const uint16_t*>(&h0);
        asm volatile("st.shared.u16 [%0], %1;" :: "r"(bbufBase0 + fragOff), "h"(hb));
    }
    __syncthreads();   // h(0) visible; step 0 needs no handoff syncs

    // per-lane Xg pointer: 8B per (m, hcol)
    const uint2* xgp = reinterpret_cast<const uint2*>(g_XgH);
    uint2 xcur = __ldg(&xgp[(size_t)n * 128 + col]);     // t = 0

    // B-fragment read base: 4 x LDS.128 at slot lane&15 (lanes 16-31 broadcast)
    const uint32_t bRead0 = bbufBase0 + (uint32_t)(lane & 15) * 16;
    const uint32_t bRead1 = bbufBase1 + (uint32_t)(lane & 15) * 16;

    const size_t OUT_HC = (size_t)LSEQ * NBATCH * HDIM;
    float* outp = out + (size_t)n * HDIM + col;          // advances 64K floats/step

#pragma unroll 1
    for (int t = 0; t < LSEQ; t++) {
        // state-independent long-latency work before any sync
        uint2 xnext = __ldg(&xgp[((size_t)(t + 1) * NBATCH + n) * 128 + col]);
        const float mn = (t < LSEQ - 1) ? msk[t + 1][nsel] : 1.0f;

        const int sbase = 1 + 2 * (t & 1);     // sync ids this step: sbase, sbase+1
        const uint32_t brd = (t & 1) ? bRead1 : bRead0;

        float acc[2][4], accB[2][4];
#pragma unroll
        for (int mt = 0; mt < 2; mt++)
#pragma unroll
            for (int p = 0; p < 4; p++) { acc[mt][p] = 0.0f; accB[mt][p] = 0.0f; }

        // --- chunk 0: k 0..63 (cols 0-63, published by warps 0-7) ---
        if (t) nbar_sync768(sbase);
#pragma unroll
        for (int kt2 = 0; kt2 < 2; kt2++) {
            uint32_t b0, b1, c0_, c1_;
            asm volatile("ld.shared.v4.u32 {%0,%1,%2,%3}, [%4];"
                         : "=r"(b0), "=r"(b1), "=r"(c0_), "=r"(c1_)
                         : "r"(brd + kt2 * 256));
#pragma unroll
            for (int mt = 0; mt < 2; mt++) {
                mma16816(acc[mt],  afrag[mt][2*kt2][0],   afrag[mt][2*kt2][1],
                                   afrag[mt][2*kt2][2],   afrag[mt][2*kt2][3],   b0, b1);
                mma16816(accB[mt], afrag[mt][2*kt2+1][0], afrag[mt][2*kt2+1][1],
                                   afrag[mt][2*kt2+1][2], afrag[mt][2*kt2+1][3], c0_, c1_);
            }
        }
        // --- chunk 1: k 64..127 (cols 64-127, published by warps 8-15) ---
        if (t) nbar_sync768(sbase + 1);
#pragma unroll
        for (int kt2 = 2; kt2 < 4; kt2++) {
            uint32_t b0, b1, c0_, c1_;
            asm volatile("ld.shared.v4.u32 {%0,%1,%2,%3}, [%4];"
                         : "=r"(b0), "=r"(b1), "=r"(c0_), "=r"(c1_)
                         : "r"(brd + kt2 * 256));
#pragma unroll
            for (int mt = 0; mt < 2; mt++) {
                mma16816(acc[mt],  afrag[mt][2*kt2][0],   afrag[mt][2*kt2][1],
                                   afrag[mt][2*kt2][2],   afrag[mt][2*kt2][3],   b0, b1);
                mma16816(accB[mt], afrag[mt][2*kt2+1][0], afrag[mt][2*kt2+1][1],
                                   afrag[mt][2*kt2+1][2], afrag[mt][2*kt2+1][3], c0_, c1_);
            }
        }

        // gate values for this lane's element: all in-register (parity select)
        const float gi = (hi ? acc[0][1] + accB[0][1] : acc[0][0] + accB[0][0]);
        const float gf = (hi ? acc[0][3] + accB[0][3] : acc[0][2] + accB[0][2]);
        const float gg = (hi ? acc[1][1] + accB[1][1] : acc[1][0] + accB[1][0]);
        const float go = (hi ? acc[1][3] + accB[1][3] : acc[1][2] + accB[1][2]);

        // --- epilogue: 1 element per lane (gate order i,f,g,o) ---
        const float2 x01 = __half22float2(*reinterpret_cast<__half2*>(&xcur.x));
        const float2 x23 = __half22float2(*reinterpret_cast<__half2*>(&xcur.y));

        const float i_ = sigg(gi + x01.x);
        const float f_ = sigg(gf + x01.y);
        const float g_ = tanhg(gg + x23.x);
        const float o_ = sigg(go + x23.y);
        const float cn = __fmaf_rn(f_, creg, i_ * g_);
        const float hv = o_ * tanhg(cn);

        creg = cn * mn;

        // publish next-step h into its fragment slot, then arrive (release)
        {
            const __half hm = __float2half(hv * mn);
            const uint16_t hb = *reinterpret_cast<const uint16_t*>(&hm);
            const uint32_t dst = ((t + 1) & 1) ? bbufBase1 : bbufBase0;
            asm volatile("st.shared.u16 [%0], %1;" :: "r"(dst + fragOff), "h"(hb));
        }
        nbar_arrive768(1 + 2 * ((t + 1) & 1) + myHalf);

        // long-latency tail AFTER arrive (overlaps other warps' next MMA)
        *outp = hv;
        outp += (size_t)NBATCH * HDIM;

        if (t == LSEQ - 1) {
            out[OUT_HC + (size_t)n * 256 + col]       = hv;
            out[OUT_HC + (size_t)n * 256 + 128 + col] = cn;
        }
        xcur = xnext;
    }
}

// ---------------------------------------------------------------------------
extern "C" void kernel_launch(void* const* d_in, const int* in_sizes, int n_in,
                              void* d_out, int out_size)
{
    const float* input   = (const float*)d_in[0];  // [L,N,I] fp32
    const float* hc      = (const float*)d_in[1];  // [N,2H]  fp32
    const int*   is_init = (const int*)  d_in[2];  // [L,N]   int32
    const float* Wih     = (const float*)d_in[3];  // [4H,I]
    const float* Whh     = (const float*)d_in[4];  // [4H,H]
    const float* bih     = (const float*)d_in[5];  // [4H]
    const float* bhh     = (const float*)d_in[6];  // [4H]
    float* out = (float*)d_out;                    // [L,N,H] then [N,2H]

    pregemm_kernel<<<(LSEQ * NBATCH) / 512, 512>>>(input, Wih, bih, bhh);
    lstm_rec_kernel<<<NBATCH / 4, 512>>>(hc, is_init, Whh, out);
}

// round 14
// speedup vs baseline: 1.2739x; 1.0253x over previous
#include <cuda_runtime.h>
#include <cuda_fp16.h>
#include <cstdint>
#include <cstddef>

#define LSEQ 512
#define NBATCH 512
#define IDIM 128
#define HDIM 128
#define GDIM 512   // 4*H

// Scratch: packed fp16 pre-activation input gates.
// Layout: [m = t*N+n][hcol 0..127][gate 0..3]  -> 8 bytes per (m, hcol)
// Padded by 1 step so the t+1 prefetch needs no bounds check.
__device__ __half g_XgH[(size_t)(LSEQ + 1) * NBATCH * GDIM];

// ---------------------------------------------------------------------------
// helpers
// ---------------------------------------------------------------------------
__device__ __forceinline__ uint32_t f2h2(float a, float b) {
    __half2 h = __floats2half2_rn(a, b);
    return *reinterpret_cast<uint32_t*>(&h);
}

__device__ __forceinline__ void mma16816(float* d,
    uint32_t a0, uint32_t a1, uint32_t a2, uint32_t a3,
    uint32_t b0, uint32_t b1)
{
    asm volatile(
        "mma.sync.aligned.m16n8k16.row.col.f32.f16.f16.f32 "
        "{%0,%1,%2,%3}, {%4,%5,%6,%7}, {%8,%9}, {%0,%1,%2,%3};\n"
        : "+f"(d[0]), "+f"(d[1]), "+f"(d[2]), "+f"(d[3])
        : "r"(a0), "r"(a1), "r"(a2), "r"(a3), "r"(b0), "r"(b1));
}

__device__ __forceinline__ void ldsm4(uint32_t& a0, uint32_t& a1,
                                      uint32_t& a2, uint32_t& a3, uint32_t saddr)
{
    asm volatile("ldmatrix.sync.aligned.m8n8.x4.shared.b16 {%0,%1,%2,%3}, [%4];"
                 : "=r"(a0), "=r"(a1), "=r"(a2), "=r"(a3) : "r"(saddr));
}

// hardware tanh (MUFU.TANH): 1 MUFU op
__device__ __forceinline__ float tanhg(float x) {
    float y; asm("tanh.approx.f32 %0, %1;" : "=f"(y) : "f"(x)); return y;
}
// sigmoid via tanh identity: 1 MUFU + 1 FMA
__device__ __forceinline__ float sigg(float x) {
    return __fmaf_rn(0.5f, tanhg(0.5f * x), 0.5f);
}

// half-K handoff barriers: 256 arrivers (8 warps) + 512 syncers = 768
__device__ __forceinline__ void nbar_sync768(int id) {
    asm volatile("bar.sync %0, 768;" :: "r"(id) : "memory");
}
__device__ __forceinline__ void nbar_arrive768(int id) {
    asm volatile("bar.arrive %0, 768;" :: "r"(id) : "memory");
}

// ---------------------------------------------------------------------------
// Phase 1: Xg = x@W_ih^T + (b_ih+b_hh), packed fp16 [m][hcol][gate].
// OCCUPANCY-2 version: 256 threads/block, 2 CTAs/SM (regs capped by
// __launch_bounds__(256,2)). Block-pair splits hcols: CTA even -> hcols 0-63,
// CTA odd -> 64-127 (all 4 gates each; 16B packed stores preserved).
// 256 M-rows/block, 8 subtiles of 32, double-buffered A smem, 1 barrier per
// subtile. Two co-resident CTAs interleave tensor vs memory phases.
// Grid 2048 (6.9 waves over 148 SMs).
// ---------------------------------------------------------------------------
__global__ void __launch_bounds__(256, 2)
pregemm_kernel(const float* __restrict__ x,
               const float* __restrict__ Wih,
               const float* __restrict__ bih,
               const float* __restrict__ bhh)
{
    __shared__ __half Ash[2][32][136];   // 17.4KB (x2 CTAs = 35KB/SM)

    const int tid  = threadIdx.x;
    const int warp = tid >> 5;           // 0..7
    const int lane = tid & 31;
    const int q    = lane & 3;
    const int r0   = lane >> 2;
    const int chalf = blockIdx.x & 1;                 // hcol half
    const size_t m_base = (size_t)(blockIdx.x >> 1) * 256;
    const int c0 = chalf * 64 + warp * 8 + q * 2;     // hcol pair base

    // --- B fragments: W_ih rows (gate j, hcols c0-group), loaded once ---
    uint32_t bfrag[4][8][2];
#pragma unroll
    for (int j = 0; j < 4; j++) {
        const float* wr = Wih + (size_t)(j * 128 + chalf * 64 + warp * 8 + r0) * IDIM;
#pragma unroll
        for (int kt = 0; kt < 8; kt++) {
            const int k = kt * 16 + q * 2;
            float2 w0 = *reinterpret_cast<const float2*>(wr + k);
            float2 w1 = *reinterpret_cast<const float2*>(wr + k + 8);
            bfrag[j][kt][0] = f2h2(w0.x, w0.y);
            bfrag[j][kt][1] = f2h2(w1.x, w1.y);
        }
    }

    // --- bias per gate for hcols c0, c0+1 ---
    float bx[4], by[4];
#pragma unroll
    for (int j = 0; j < 4; j++) {
        bx[j] = bih[j * 128 + c0]     + bhh[j * 128 + c0];
        by[j] = bih[j * 128 + c0 + 1] + bhh[j * 128 + c0 + 1];
    }

    // A-tile loader coords: 256 threads, thread covers 16 floats of one row
    const int lr = tid >> 3;             // 0..31
    const int lc = (tid & 7) * 16;       // 0,16,...,112

    const int lm_row = lane & 15;
    const int lm_col = (lane >> 4) * 8;

    // prefetch subtile 0 (4 float4 per thread)
    float4 v0 = *reinterpret_cast<const float4*>(x + (m_base + lr) * IDIM + lc);
    float4 v1 = *reinterpret_cast<const float4*>(x + (m_base + lr) * IDIM + lc + 4);
    float4 v2 = *reinterpret_cast<const float4*>(x + (m_base + lr) * IDIM + lc + 8);
    float4 v3 = *reinterpret_cast<const float4*>(x + (m_base + lr) * IDIM + lc + 12);

#pragma unroll 1
    for (int s = 0; s < 8; s++) {
        const int buf = s & 1;
        {
            __half2* sp = reinterpret_cast<__half2*>(&Ash[buf][lr][lc]);
            sp[0] = __floats2half2_rn(v0.x, v0.y);
            sp[1] = __floats2half2_rn(v0.z, v0.w);
            sp[2] = __floats2half2_rn(v1.x, v1.y);
            sp[3] = __floats2half2_rn(v1.z, v1.w);
            sp[4] = __floats2half2_rn(v2.x, v2.y);
            sp[5] = __floats2half2_rn(v2.z, v2.w);
            sp[6] = __floats2half2_rn(v3.x, v3.y);
            sp[7] = __floats2half2_rn(v3.z, v3.w);
        }
        __syncthreads();    // single barrier per subtile

        if (s < 7) {
            const size_t mr = m_base + (s + 1) * 32 + lr;
            v0 = *reinterpret_cast<const float4*>(x + mr * IDIM + lc);
            v1 = *reinterpret_cast<const float4*>(x + mr * IDIM + lc + 4);
            v2 = *reinterpret_cast<const float4*>(x + mr * IDIM + lc + 8);
            v3 = *reinterpret_cast<const float4*>(x + mr * IDIM + lc + 12);
        }

        float acc[2][4][4];
#pragma unroll
        for (int mi = 0; mi < 2; mi++)
#pragma unroll
            for (int j = 0; j < 4; j++)
#pragma unroll
                for (int p = 0; p < 4; p++) acc[mi][j][p] = 0.0f;

#pragma unroll
        for (int kt = 0; kt < 8; kt++) {
#pragma unroll
            for (int mi = 0; mi < 2; mi++) {
                uint32_t a0, a1, a2, a3;
                uint32_t saddr = (uint32_t)__cvta_generic_to_shared(
                    &Ash[buf][mi * 16 + lm_row][kt * 16 + lm_col]);
                ldsm4(a0, a1, a2, a3, saddr);
#pragma unroll
                for (int j = 0; j < 4; j++)
                    mma16816(acc[mi][j], a0, a1, a2, a3, bfrag[j][kt][0], bfrag[j][kt][1]);
            }
        }

        const size_t m0 = m_base + s * 32;
#pragma unroll
        for (int mi = 0; mi < 2; mi++) {
#pragma unroll
            for (int half_ = 0; half_ < 2; half_++) {
                const size_t row = m0 + mi * 16 + r0 + half_ * 8;
                const int pa = half_ * 2;
                uint4 v;
                v.x = f2h2(acc[mi][0][pa]     + bx[0], acc[mi][1][pa]     + bx[1]);
                v.y = f2h2(acc[mi][2][pa]     + bx[2], acc[mi][3][pa]     + bx[3]);
                v.z = f2h2(acc[mi][0][pa + 1] + by[0], acc[mi][1][pa + 1] + by[1]);
                v.w = f2h2(acc[mi][2][pa + 1] + by[2], acc[mi][3][pa + 1] + by[3]);
                *reinterpret_cast<uint4*>(&g_XgH[(row * 128 + c0) * 4]) = v;
            }
        }
    }
}

// ---------------------------------------------------------------------------
// Phase 2: masked LSTM recurrence — R12 exactly (best proven: 317us).
// Transposed W-stationary GEMM, pre-fragmented B, gate-interleaved tiles,
// in-register gate epilogue, half-K handoff named barriers.
// Grid 128 blocks x 4 batch rows, 512 threads, 16 MMA/warp/step.
// ---------------------------------------------------------------------------
__global__ void __launch_bounds__(512, 1)
lstm_rec_kernel(const float* __restrict__ hc,
                const int*   __restrict__ is_init,
                const float* __restrict__ Whh,
                float* __restrict__ out)
{
    __shared__ uint4 bbuf[2][4][16];      // pre-fragmented h, kt-pairs packed (2KB)
    __shared__ float msk[LSEQ][4];        // mask table (8KB)

    const int tid  = threadIdx.x;
    const int warp = tid >> 5;
    const int lane = tid & 31;
    const int q    = lane & 3;
    const int r0   = lane >> 2;
    const int n0   = blockIdx.x * 4;

    // in-register element ownership: lane (r0,q) -> (col, nsel)
    const int col  = warp * 8 + r0;             // global hcol
    const int nsel = 2 * (q & 1) + (q >> 1);    // batch row 0..3
    const int hi   = q >> 1;                    // accumulator parity
    const int n    = n0 + nsel;
    const int myHalf = warp >> 3;               // which handoff barrier I feed

    // fragment-slot byte offset (within one buf) for this lane's h element:
    // bbuf[buf][kt2][l16] 16B slot: +0..7 = kt even (b0@+0/b1@+4), +8..15 = kt odd
    const int fkt  = col >> 4;
    const int fr   = col & 15;
    const int fl16 = nsel * 4 + ((fr & 7) >> 1);
    const uint32_t fragOff = (uint32_t)((((fkt >> 1) * 16 + fl16) * 16) +
                                        (fkt & 1) * 8 +
                                        ((fr & 8) ? 4 : 0) + (col & 1) * 2);
    const uint32_t bbufBase0 = (uint32_t)__cvta_generic_to_shared(&bbuf[0][0][0]);
    const uint32_t bbufBase1 = (uint32_t)__cvta_generic_to_shared(&bbuf[1][0][0]);

    // --- A-fragments (gate-interleaved tiles), loaded once ---
    uint32_t afrag[2][8][4];
#pragma unroll
    for (int mt = 0; mt < 2; mt++) {
        const float* wlo = Whh + (size_t)((2 * mt)     * 128 + warp * 8 + r0) * HDIM;
        const float* whi = Whh + (size_t)((2 * mt + 1) * 128 + warp * 8 + r0) * HDIM;
#pragma unroll
        for (int kt = 0; kt < 8; kt++) {
            const int k = kt * 16 + q * 2;
            float2 w00 = *reinterpret_cast<const float2*>(wlo + k);
            float2 w01 = *reinterpret_cast<const float2*>(wlo + k + 8);
            float2 w10 = *reinterpret_cast<const float2*>(whi + k);
            float2 w11 = *reinterpret_cast<const float2*>(whi + k + 8);
            afrag[mt][kt][0] = f2h2(w00.x, w00.y);   // row r0     (gate 2mt)
            afrag[mt][kt][1] = f2h2(w10.x, w10.y);   // row r0+8   (gate 2mt+1)
            afrag[mt][kt][2] = f2h2(w01.x, w01.y);
            afrag[mt][kt][3] = f2h2(w11.x, w11.y);
        }
    }

    // --- mask table ---
    for (int idx = tid; idx < LSEQ * 4; idx += 512) {
        const int t = idx >> 2, r = idx & 3;
        msk[t][r] = 1.0f - (float)is_init[(size_t)t * NBATCH + n0 + r];
    }
    __syncthreads();

    // --- init state (t=0 mask applied); write h0 into fragment slot ---
    const float m0v = msk[0][nsel];
    float creg = hc[(size_t)n * 256 + 128 + col] * m0v;
    {
        const __half h0 = __float2half(hc[(size_t)n * 256 + col] * m0v);
        const uint16_t hb = *reinterpret_cast<const uint16_t*>(&h0);
        asm volatile("st.shared.u16 [%0], %1;" :: "r"(bbufBase0 + fragOff), "h"(hb));
    }
    __syncthreads();   // h(0) visible; step 0 needs no handoff syncs

    // per-lane Xg pointer: 8B per (m, hcol)
    const uint2* xgp = reinterpret_cast<const uint2*>(g_XgH);
    uint2 xcur = __ldg(&xgp[(size_t)n * 128 + col]);     // t = 0

    // B-fragment read base: 4 x LDS.128 at slot lane&15 (lanes 16-31 broadcast)
    const uint32_t bRead0 = bbufBase0 + (uint32_t)(lane & 15) * 16;
    const uint32_t bRead1 = bbufBase1 + (uint32_t)(lane & 15) * 16;

    const size_t OUT_HC = (size_t)LSEQ * NBATCH * HDIM;
    float* outp = out + (size_t)n * HDIM + col;          // advances 64K floats/step

#pragma unroll 1
    for (int t = 0; t < LSEQ; t++) {
        // state-independent long-latency work before any sync
        uint2 xnext = __ldg(&xgp[((size_t)(t + 1) * NBATCH + n) * 128 + col]);
        const float mn = (t < LSEQ - 1) ? msk[t + 1][nsel] : 1.0f;

        const int sbase = 1 + 2 * (t & 1);     // sync ids this step: sbase, sbase+1
        const uint32_t brd = (t & 1) ? bRead1 : bRead0;

        float acc[2][4], accB[2][4];
#pragma unroll
        for (int mt = 0; mt < 2; mt++)
#pragma unroll
            for (int p = 0; p < 4; p++) { acc[mt][p] = 0.0f; accB[mt][p] = 0.0f; }

        // --- chunk 0: k 0..63 (cols 0-63, published by warps 0-7) ---
        if (t) nbar_sync768(sbase);
#pragma unroll
        for (int kt2 = 0; kt2 < 2; kt2++) {
            uint32_t b0, b1, c0_, c1_;
            asm volatile("ld.shared.v4.u32 {%0,%1,%2,%3}, [%4];"
                         : "=r"(b0), "=r"(b1), "=r"(c0_), "=r"(c1_)
                         : "r"(brd + kt2 * 256));
#pragma unroll
            for (int mt = 0; mt < 2; mt++) {
                mma16816(acc[mt],  afrag[mt][2*kt2][0],   afrag[mt][2*kt2][1],
                                   afrag[mt][2*kt2][2],   afrag[mt][2*kt2][3],   b0, b1);
                mma16816(accB[mt], afrag[mt][2*kt2+1][0], afrag[mt][2*kt2+1][1],
                                   afrag[mt][2*kt2+1][2], afrag[mt][2*kt2+1][3], c0_, c1_);
            }
        }
        // --- chunk 1: k 64..127 (cols 64-127, published by warps 8-15) ---
        if (t) nbar_sync768(sbase + 1);
#pragma unroll
        for (int kt2 = 2; kt2 < 4; kt2++) {
            uint32_t b0, b1, c0_, c1_;
            asm volatile("ld.shared.v4.u32 {%0,%1,%2,%3}, [%4];"
                         : "=r"(b0), "=r"(b1), "=r"(c0_), "=r"(c1_)
                         : "r"(brd + kt2 * 256));
#pragma unroll
            for (int mt = 0; mt < 2; mt++) {
                mma16816(acc[mt],  afrag[mt][2*kt2][0],   afrag[mt][2*kt2][1],
                                   afrag[mt][2*kt2][2],   afrag[mt][2*kt2][3],   b0, b1);
                mma16816(accB[mt], afrag[mt][2*kt2+1][0], afrag[mt][2*kt2+1][1],
                                   afrag[mt][2*kt2+1][2], afrag[mt][2*kt2+1][3], c0_, c1_);
            }
        }

        // gate values for this lane's element: all in-register (parity select)
        const float gi = (hi ? acc[0][1] + accB[0][1] : acc[0][0] + accB[0][0]);
        const float gf = (hi ? acc[0][3] + accB[0][3] : acc[0][2] + accB[0][2]);
        const float gg = (hi ? acc[1][1] + accB[1][1] : acc[1][0] + accB[1][0]);
        const float go = (hi ? acc[1][3] + accB[1][3] : acc[1][2] + accB[1][2]);

        // --- epilogue: 1 element per lane (gate order i,f,g,o) ---
        const float2 x01 = __half22float2(*reinterpret_cast<__half2*>(&xcur.x));
        const float2 x23 = __half22float2(*reinterpret_cast<__half2*>(&xcur.y));

        const float i_ = sigg(gi + x01.x);
        const float f_ = sigg(gf + x01.y);
        const float g_ = tanhg(gg + x23.x);
        const float o_ = sigg(go + x23.y);
        const float cn = __fmaf_rn(f_, creg, i_ * g_);
        const float hv = o_ * tanhg(cn);

        creg = cn * mn;

        // publish next-step h into its fragment slot, then arrive (release)
        {
            const __half hm = __float2half(hv * mn);
            const uint16_t hb = *reinterpret_cast<const uint16_t*>(&hm);
            const uint32_t dst = ((t + 1) & 1) ? bbufBase1 : bbufBase0;
            asm volatile("st.shared.u16 [%0], %1;" :: "r"(dst + fragOff), "h"(hb));
        }
        nbar_arrive768(1 + 2 * ((t + 1) & 1) + myHalf);

        // long-latency tail AFTER arrive (overlaps other warps' next MMA)
        *outp = hv;
        outp += (size_t)NBATCH * HDIM;

        if (t == LSEQ - 1) {
            out[OUT_HC + (size_t)n * 256 + col]       = hv;
            out[OUT_HC + (size_t)n * 256 + 128 + col] = cn;
        }
        xcur = xnext;
    }
}

// ---------------------------------------------------------------------------
extern "C" void kernel_launch(void* const* d_in, const int* in_sizes, int n_in,
                              void* d_out, int out_size)
{
    const float* input   = (const float*)d_in[0];  // [L,N,I] fp32
    const float* hc      = (const float*)d_in[1];  // [N,2H]  fp32
    const int*   is_init = (const int*)  d_in[2];  // [L,N]   int32
    const float* Wih     = (const float*)d_in[3];  // [4H,I]
    const float* Whh     = (const float*)d_in[4];  // [4H,H]
    const float* bih     = (const float*)d_in[5];  // [4H]
    const float* bhh     = (const float*)d_in[6];  // [4H]
    float* out = (float*)d_out;                    // [L,N,H] then [N,2H]

    pregemm_kernel<<<(LSEQ * NBATCH / 256) * 2, 256>>>(input, Wih, bih, bhh);
    lstm_rec_kernel<<<NBATCH / 4, 512>>>(hc, is_init, Whh, out);
}